// round 14
// baseline (speedup 1.0000x reference)
#include <cuda_runtime.h>
#include <cuda_fp16.h>
#include <math.h>
#include <stdint.h>

// ---------------------------------------------------------------------------
// GraphDecoder on tensor cores (mma.sync fp16, hi/lo split, fp32 acc).
// Round 14:
//  - qkv back to ks=1 (R13's split-K2 was traffic-neutral-negative)
//  - warp-per-row add_ln (no block barriers)
//  - obj->fp16 fused into mlp2 epilogue (obj_split kernel deleted)
//  - encoder/MLP fp16 3-term; relation single-term fp16 + fused Wv (kept)
// ---------------------------------------------------------------------------

#define LL  8
#define SS  128
#define DD  512
#define HH  8
#define HDD 64
#define NT  1024

typedef __half f16;

// ---- persistent scratch ----------------------------------------------------
#define OFF_AIW 0            // 3 x 786432
#define OFF_AOW 2359296      // 3 x 262144
#define OFF_F1W 3145728      // 3 x 1048576
#define OFF_F2W 6291456      // 3 x 1048576
#define OFF_W0  9437184      // 4 x 262144
#define OFF_W1  10485760
#define OFF_W2  11534336
#define WTOT    12582912

#define PSTR  (NT * DD)           // 524288 floats per partial slab

__device__ f16   g_wh[WTOT], g_wl[WTOT];
__device__ f16   g_s0h[4 * NT * DD], g_s0l[4 * NT * DD];
__device__ f16   g_s1h[4 * NT * DD], g_s1l[4 * NT * DD];
__device__ float g_h[NT * DD];
__device__ float g_qkv[NT * 3 * DD];
__device__ float g_part[8 * NT * DD];      // split-K / batch partial arena

// ========================= low-level helpers ================================
__device__ __forceinline__ uint32_t smem_u32(const void* p) {
    uint32_t a;
    asm("{ .reg .u64 t; cvta.to.shared.u64 t, %1; cvt.u32.u64 %0, t; }"
        : "=r"(a) : "l"(p));
    return a;
}

// swizzle for 64-byte rows: XOR bits [4:6) with bits [7:9)
__device__ __forceinline__ uint32_t swz(uint32_t off) {
    return off ^ (((off >> 7) & 3u) << 4);
}

__device__ __forceinline__ void ldmx4(uint32_t* r, uint32_t addr) {
    asm volatile("ldmatrix.sync.aligned.m8n8.x4.shared.b16 {%0,%1,%2,%3}, [%4];"
        : "=r"(r[0]), "=r"(r[1]), "=r"(r[2]), "=r"(r[3]) : "r"(addr));
}

__device__ __forceinline__ void mma16816(float* d, const uint32_t* a,
                                         const uint32_t* b) {
    asm volatile(
        "mma.sync.aligned.m16n8k16.row.col.f32.f16.f16.f32 "
        "{%0,%1,%2,%3}, {%4,%5,%6,%7}, {%8,%9}, {%0,%1,%2,%3};"
        : "+f"(d[0]), "+f"(d[1]), "+f"(d[2]), "+f"(d[3])
        : "r"(a[0]), "r"(a[1]), "r"(a[2]), "r"(a[3]), "r"(b[0]), "r"(b[1]));
}

__device__ __forceinline__ void cp16(uint32_t smem, const void* g) {
    asm volatile("cp.async.cg.shared.global [%0], [%1], 16;"
        :: "r"(smem), "l"(g));
}
#define CP_COMMIT asm volatile("cp.async.commit_group;" ::: "memory")
#define CP_WAIT1  asm volatile("cp.async.wait_group 1;" ::: "memory")
#define CP_WAIT2  asm volatile("cp.async.wait_group 2;" ::: "memory")

__device__ __forceinline__ void split2(float x, float y, uint32_t& hi, uint32_t& lo) {
    __half2 h, l;
    h.x = __float2half(x); h.y = __float2half(y);
    l.x = __float2half(x - __half2float(h.x));
    l.y = __float2half(y - __half2float(h.y));
    hi = *(uint32_t*)&h; lo = *(uint32_t*)&l;
}

__device__ __forceinline__ uint32_t pack2(float x, float y) {
    __half2 h;
    h.x = __float2half(x); h.y = __float2half(y);
    return *(uint32_t*)&h;
}

#define TILE_B  8192   // 128x32 f16 tile
#define TILE64  4096   // 64x32 f16 tile

// ---------------------------------------------------------------------------
// GEMM tile-mma (64x64, 4 warps 2m x 2n): A both-kk prefetch, term-outermost.
// ---------------------------------------------------------------------------
__device__ __forceinline__ void tile_mma44(
    uint32_t ahB, uint32_t alB, uint32_t bhB, uint32_t blB,
    const uint32_t* a0, const uint32_t* a1, const uint32_t (*bo)[2],
    float (&acc)[2][4][4])
{
    uint32_t ah[2][2][4], al[2][2][4];   // [kk][mt][4]
#pragma unroll
    for (int kk = 0; kk < 2; ++kk) {
        ldmx4(ah[kk][0], ahB + a0[kk]);
        ldmx4(ah[kk][1], ahB + a1[kk]);
        ldmx4(al[kk][0], alB + a0[kk]);
        ldmx4(al[kk][1], alB + a1[kk]);
    }
#pragma unroll
    for (int kk = 0; kk < 2; ++kk) {
        uint32_t bh[4][2], bl[4][2];
#pragma unroll
        for (int ng = 0; ng < 2; ++ng) {
            uint32_t r[4];
            ldmx4(r, bhB + bo[ng][kk]);
            bh[2*ng][0] = r[0]; bh[2*ng][1] = r[1];
            bh[2*ng+1][0] = r[2]; bh[2*ng+1][1] = r[3];
            ldmx4(r, blB + bo[ng][kk]);
            bl[2*ng][0] = r[0]; bl[2*ng][1] = r[1];
            bl[2*ng+1][0] = r[2]; bl[2*ng+1][1] = r[3];
        }
#pragma unroll
        for (int mt = 0; mt < 2; ++mt)
#pragma unroll
            for (int nt = 0; nt < 4; ++nt)
                mma16816(acc[mt][nt], ah[kk][mt], bh[nt]);
#pragma unroll
        for (int mt = 0; mt < 2; ++mt)
#pragma unroll
            for (int nt = 0; nt < 4; ++nt)
                mma16816(acc[mt][nt], ah[kk][mt], bl[nt]);
#pragma unroll
        for (int mt = 0; mt < 2; ++mt)
#pragma unroll
            for (int nt = 0; nt < 4; ++nt)
                mma16816(acc[mt][nt], al[kk][mt], bh[nt]);
    }
}

// ---------------------------------------------------------------------------
// Relation tile-mma (128x128, SINGLE term): acc[2][8][4].
// ---------------------------------------------------------------------------
__device__ __forceinline__ void tile_mma_rel(
    uint32_t ahB, uint32_t bhB,
    const uint32_t* a0, const uint32_t* a1, const uint32_t (*bo)[2],
    float (&acc)[2][8][4])
{
#pragma unroll
    for (int kk = 0; kk < 2; ++kk) {
        uint32_t ah[2][4];
        ldmx4(ah[0], ahB + a0[kk]);
        ldmx4(ah[1], ahB + a1[kk]);
#pragma unroll
        for (int hf = 0; hf < 2; ++hf) {
            uint32_t bh[4][2];
#pragma unroll
            for (int ng = 0; ng < 2; ++ng) {
                uint32_t r[4];
                ldmx4(r, bhB + bo[2 * hf + ng][kk]);
                bh[2*ng][0] = r[0]; bh[2*ng][1] = r[1];
                bh[2*ng+1][0] = r[2]; bh[2*ng+1][1] = r[3];
            }
#pragma unroll
            for (int mt = 0; mt < 2; ++mt)
#pragma unroll
                for (int nt = 0; nt < 4; ++nt)
                    mma16816(acc[mt][4*hf + nt], ah[mt], bh[nt]);
        }
    }
}

// ---------------------------------------------------------------------------
// f16 GEMM (3-term), batched (z) + split-K (ks).
// 64x64 tile, 128 threads, BK=32, 3-stage ring, ONE sync/chunk, 4 CTAs/SM.
// Output modes: (Ch&&Cl) fp16 hi/lo; else fp32 Cf, plus fp16-hi to Ch
// for batch z == f16z (fused obj split).
// ---------------------------------------------------------------------------
#define G_AH 0
#define G_AL 4096
#define G_BH 8192
#define G_BL 12288
#define STAGE_BYTES 16384
#define GEMM_SMEM   (3 * STAGE_BYTES + 128)   // 49280

__global__ void __launch_bounds__(128, 4) gemm_f16_kernel(
    const f16* __restrict__ Ah, const f16* __restrict__ Al,
    const f16* __restrict__ Wh, const f16* __restrict__ Wl,
    const float* __restrict__ bias,
    float* __restrict__ Cf, f16* __restrict__ Ch, f16* __restrict__ Cl,
    int N, int K, int relu, int ks, int pstr, int f16z,
    int zsA, int zsW, int zsB, int zsC)
{
    extern __shared__ char smch[];
    const uint32_t base = (smem_u32(smch) + 127) & ~127u;

    const int z  = blockIdx.z / ks;
    const int kz = blockIdx.z % ks;
    const int Klocal = K / ks;
    const int kbase = kz * Klocal;

    Ah += (size_t)z * zsA;  Al += (size_t)z * zsA;
    Wh += (size_t)z * zsW;  Wl += (size_t)z * zsW;
    bias += (size_t)z * zsB;
    if (Cf) Cf += (size_t)z * zsC + (size_t)kz * pstr;
    if (Ch && Cl) { Ch += (size_t)z * zsC; Cl += (size_t)z * zsC; }

    const int tid  = threadIdx.x;
    const int lane = tid & 31;
    const int wid  = tid >> 5;
    const int wm   = wid & 1;
    const int wn   = wid >> 1;
    const int m0 = blockIdx.y * 64;
    const int n0 = blockIdx.x * 64;

    const f16* gsrc[8];
    uint32_t sdst[8];
#pragma unroll
    for (int it = 0; it < 8; ++it) {
        int c = tid + it * 128;
        int a = c >> 8;
        int idx = c & 255;
        int row = idx >> 2;
        int q   = idx & 3;
        const f16* p;
        if (a == 0)      p = Ah + (size_t)(m0 + row) * K;
        else if (a == 1) p = Al + (size_t)(m0 + row) * K;
        else if (a == 2) p = Wh + (size_t)(n0 + row) * K;
        else             p = Wl + (size_t)(n0 + row) * K;
        gsrc[it] = p + kbase + q * 8;
        sdst[it] = a * TILE64 + swz(row * 64 + q * 16);
    }

    const int nch = Klocal >> 5;
    auto issue = [&](int s) {
        uint32_t st = base + (s % 3) * STAGE_BYTES;
#pragma unroll
        for (int it = 0; it < 8; ++it)
            cp16(st + sdst[it], gsrc[it] + s * 32);
    };
    issue(0); CP_COMMIT;
    issue(1); CP_COMMIT;

    const int aRow = wm * 32 + (lane & 15);
    const int aCol = (lane >> 4) * 8;
    const int bRow = wn * 32 + (lane & 7) + ((lane >> 4) << 3);
    const int bCol = ((lane >> 3) & 1) * 8;
    uint32_t a0[2], a1[2], bo[2][2];
#pragma unroll
    for (int kk = 0; kk < 2; ++kk) {
        a0[kk] = swz(aRow * 64 + aCol * 2 + kk * 32);
        a1[kk] = swz((aRow + 16) * 64 + aCol * 2 + kk * 32);
#pragma unroll
        for (int ng = 0; ng < 2; ++ng)
            bo[ng][kk] = swz((bRow + ng * 16) * 64 + bCol * 2 + kk * 32);
    }

    float acc[2][4][4] = {};

    for (int s = 0; s < nch; ++s) {
        CP_WAIT1;
        __syncthreads();
        if (s + 2 < nch) issue(s + 2);
        CP_COMMIT;
        uint32_t st = base + (s % 3) * STAGE_BYTES;
        tile_mma44(st + G_AH, st + G_AL, st + G_BH, st + G_BL,
                   a0, a1, bo, acc);
    }

    const int addb = (kz == 0);
    const bool hilo = (Ch != nullptr) && (Cl != nullptr);
    const bool fhi  = (Ch != nullptr) && (Cl == nullptr) && (z == f16z);
#pragma unroll
    for (int mt = 0; mt < 2; ++mt) {
        int r0 = m0 + wm * 32 + mt * 16 + (lane >> 2);
#pragma unroll
        for (int nt = 0; nt < 4; ++nt) {
            int col = n0 + wn * 32 + nt * 8 + (lane & 3) * 2;
            float b0 = addb ? bias[col] : 0.f, b1 = addb ? bias[col + 1] : 0.f;
            float v0 = acc[mt][nt][0] + b0, v1 = acc[mt][nt][1] + b1;
            float v2 = acc[mt][nt][2] + b0, v3 = acc[mt][nt][3] + b1;
            if (relu) {
                v0 = fmaxf(v0, 0.f); v1 = fmaxf(v1, 0.f);
                v2 = fmaxf(v2, 0.f); v3 = fmaxf(v3, 0.f);
            }
            if (hilo) {
                uint32_t hh, ll;
                split2(v0, v1, hh, ll);
                *(uint32_t*)&Ch[(size_t)r0 * N + col] = hh;
                *(uint32_t*)&Cl[(size_t)r0 * N + col] = ll;
                split2(v2, v3, hh, ll);
                *(uint32_t*)&Ch[(size_t)(r0 + 8) * N + col] = hh;
                *(uint32_t*)&Cl[(size_t)(r0 + 8) * N + col] = ll;
            } else {
                *(float2*)&Cf[(size_t)r0 * N + col]       = make_float2(v0, v1);
                *(float2*)&Cf[(size_t)(r0 + 8) * N + col] = make_float2(v2, v3);
                if (fhi) {
                    *(uint32_t*)&Ch[(size_t)r0 * N + col]       = pack2(v0, v1);
                    *(uint32_t*)&Ch[(size_t)(r0 + 8) * N + col] = pack2(v2, v3);
                }
            }
        }
    }
}

// ---------------------------------------------------------------------------
// Relation tensor (single-term fp16): out[b,i,:,:] = ((sub_b * W_bi) @ obj_b^T)
// W_bi = vsub[b,i,:] * vobj[b,i,:] computed in the ws prologue.
// ---------------------------------------------------------------------------
#define RA_STAGE TILE_B     // Ah only
#define RB_STAGE TILE_B     // Bh only
#define REL_SMEM (2048 + 2 * RA_STAGE + 3 * RB_STAGE + 128)  // 43136

__global__ void __launch_bounds__(256, 2) final_tc_kernel(
    const float* __restrict__ sub, const f16* __restrict__ objh,
    const float* __restrict__ vsub, const float* __restrict__ vobj,
    float* __restrict__ out)
{
    extern __shared__ char smch[];
    const uint32_t sb = (smem_u32(smch) + 127) & ~127u;
    float* ws = (float*)(smch + (sb - smem_u32(smch)));
    char* aPtr = (char*)ws + 2048;
    const uint32_t aBase = sb + 2048;
    const uint32_t bBase = aBase + 2 * RA_STAGE;

    const int i = blockIdx.x;
    const int b = blockIdx.y;
    const int tid  = threadIdx.x;
    const int lane = tid & 31;
    const int wid  = tid >> 5;
    const int wm   = wid & 3;
    const int wn   = wid >> 2;

    // W row = vsub * vobj (fused)
    {
        const size_t rb = (size_t)(b * SS + i) * DD;
        float2 a0v = *(const float2*)&vsub[rb + 2 * tid];
        float2 b0v = *(const float2*)&vobj[rb + 2 * tid];
        ws[2 * tid]     = a0v.x * b0v.x;
        ws[2 * tid + 1] = a0v.y * b0v.y;
    }

    const float* subB = sub + (size_t)b * SS * DD;
    const f16* ohB = objh + (size_t)b * SS * DD;

    const f16* bsrc[2];
    uint32_t bdst[2];
#pragma unroll
    for (int it = 0; it < 2; ++it) {
        int c = tid + it * 256;
        int row = c >> 2, q = c & 3;
        bsrc[it] = ohB + (size_t)row * DD + q * 8;
        bdst[it] = swz(row * 64 + q * 16);
    }
    int aLrow[4], aLc4[4];
#pragma unroll
    for (int it = 0; it < 4; ++it) {
        int idx = tid + it * 256;
        aLrow[it] = idx >> 3;
        aLc4[it]  = (idx & 7) << 2;
    }

    auto issueB = [&](int s) {
        uint32_t st = bBase + (s % 3) * RB_STAGE;
#pragma unroll
        for (int it = 0; it < 2; ++it)
            cp16(st + bdst[it], bsrc[it] + s * 32);
    };
    auto loadA = [&](int s, float4* r) {
#pragma unroll
        for (int it = 0; it < 4; ++it)
            r[it] = *(const float4*)&subB[(size_t)aLrow[it] * DD + s * 32 + aLc4[it]];
    };
    auto storeA = [&](int s, const float4* r) {
        char* dh = aPtr + (s & 1) * RA_STAGE;
        int kc = s * 32;
#pragma unroll
        for (int it = 0; it < 4; ++it) {
            float4 v = r[it];
            v.x *= ws[kc + aLc4[it]];     v.y *= ws[kc + aLc4[it] + 1];
            v.z *= ws[kc + aLc4[it] + 2]; v.w *= ws[kc + aLc4[it] + 3];
            uint32_t h0 = pack2(v.x, v.y);
            uint32_t h1 = pack2(v.z, v.w);
            uint32_t off = swz(aLrow[it] * 64 + aLc4[it] * 2);
            *(uint2*)(dh + off) = make_uint2(h0, h1);
        }
    };

    issueB(0); CP_COMMIT;
    issueB(1); CP_COMMIT;
    issueB(2); CP_COMMIT;
    __syncthreads();              // ws visible
    {
        float4 r0[4];
        loadA(0, r0);
        storeA(0, r0);
    }

    const int aRow = wm * 32 + (lane & 15);
    const int aCol = (lane >> 4) * 8;
    const int bRow = wn * 64 + (lane & 7) + ((lane >> 4) << 3);
    const int bCol = ((lane >> 3) & 1) * 8;
    uint32_t a0[2], a1[2], bo[4][2];
#pragma unroll
    for (int kk = 0; kk < 2; ++kk) {
        a0[kk] = swz(aRow * 64 + aCol * 2 + kk * 32);
        a1[kk] = swz((aRow + 16) * 64 + aCol * 2 + kk * 32);
#pragma unroll
        for (int ng = 0; ng < 4; ++ng)
            bo[ng][kk] = swz((bRow + ng * 16) * 64 + bCol * 2 + kk * 32);
    }

    float acc[2][8][4] = {};
    float4 pre[4];

    for (int s = 0; s < 16; ++s) {
        if (s + 1 < 16) loadA(s + 1, pre);
        CP_WAIT2;
        __syncthreads();
        uint32_t aB = aBase + (s & 1) * RA_STAGE;
        uint32_t bB = bBase + (s % 3) * RB_STAGE;
        tile_mma_rel(aB, bB, a0, a1, bo, acc);
        __syncthreads();
        if (s + 1 < 16) storeA(s + 1, pre);
        if (s + 3 < 16) issueB(s + 3);
        CP_COMMIT;
    }

    float* outB = out + (size_t)(b * SS + i) * SS * SS;
#pragma unroll
    for (int mt = 0; mt < 2; ++mt) {
        int r0 = wm * 32 + mt * 16 + (lane >> 2);
#pragma unroll
        for (int nt = 0; nt < 8; ++nt) {
            int col = wn * 64 + nt * 8 + (lane & 3) * 2;
            *(float2*)&outB[(size_t)r0 * SS + col] =
                make_float2(acc[mt][nt][0], acc[mt][nt][1]);
            *(float2*)&outB[(size_t)(r0 + 8) * SS + col] =
                make_float2(acc[mt][nt][2], acc[mt][nt][3]);
        }
    }
}

// ---------------------------------------------------------------------------
// Attention over axis L per (s, h); single qkv buffer; fp16 hi/lo out.
// ---------------------------------------------------------------------------
__global__ void attn_kernel(const float* __restrict__ qkv,
                            f16* __restrict__ oh, f16* __restrict__ ol)
{
    const int s = blockIdx.x;
    const int h = blockIdx.y;
    const int t = threadIdx.x;  // 0..63

    __shared__ float qs[8][65], ks[8][65], vs[8][65];
    __shared__ float at[8][9];

#pragma unroll
    for (int l = 0; l < 8; ++l) {
        size_t base = (size_t)(l * SS + s) * (3 * DD) + h * HDD + t;
        qs[l][t] = qkv[base];
        ks[l][t] = qkv[base + DD];
        vs[l][t] = qkv[base + 2 * DD];
    }
    __syncthreads();

    const int l = t >> 3;
    const int m = t & 7;
    float sc = 0.0f;
#pragma unroll
    for (int d = 0; d < HDD; ++d) sc += qs[l][d] * ks[m][d];
    sc *= 0.125f;

    float mx = sc;
#pragma unroll
    for (int off = 1; off < 8; off <<= 1)
        mx = fmaxf(mx, __shfl_xor_sync(0xffffffffu, mx, off));
    float e = __expf(sc - mx);
    float sm = e;
#pragma unroll
    for (int off = 1; off < 8; off <<= 1)
        sm += __shfl_xor_sync(0xffffffffu, sm, off);
    at[l][m] = e / sm;
    __syncthreads();

    const int dg = (t & 7) * 8;
    float accv[8] = {};
#pragma unroll
    for (int mm = 0; mm < 8; ++mm) {
        float a = at[l][mm];
#pragma unroll
        for (int j = 0; j < 8; ++j)
            accv[j] = fmaf(a, vs[mm][dg + j], accv[j]);
    }
    size_t ob = (size_t)(l * SS + s) * DD + h * HDD + dg;
#pragma unroll
    for (int j = 0; j < 8; j += 2) {
        uint32_t hh, ll;
        split2(accv[j], accv[j + 1], hh, ll);
        *(uint32_t*)&oh[ob + j] = hh;
        *(uint32_t*)&ol[ob + j] = ll;
    }
}

// ---------------------------------------------------------------------------
// Warp-per-row add_ln: out = LayerNorm(a + sum_{p<np} P[p*pstr+.]).
// 256 threads = 8 warps = 8 rows per block; no block barriers.
// Each lane owns 16 columns (4x float4, stride 128).
// ---------------------------------------------------------------------------
__global__ void add_ln_kernel(const float* __restrict__ a,
                              const float* __restrict__ P, int np, int pstr,
                              const float* __restrict__ gam, const float* __restrict__ bet,
                              float* __restrict__ out,
                              f16* __restrict__ outh, f16* __restrict__ outl)
{
    const int lane = threadIdx.x & 31;
    const int row  = blockIdx.x * 8 + (threadIdx.x >> 5);
    const size_t base = (size_t)row * DD;

    float4 v[4];
#pragma unroll
    for (int c = 0; c < 4; ++c)
        v[c] = *(const float4*)&a[base + c * 128 + lane * 4];
    for (int p = 0; p < np; ++p) {
        const float* Pp = P + (size_t)p * pstr + base;
#pragma unroll
        for (int c = 0; c < 4; ++c) {
            float4 x = *(const float4*)&Pp[c * 128 + lane * 4];
            v[c].x += x.x; v[c].y += x.y; v[c].z += x.z; v[c].w += x.w;
        }
    }

    float s = 0.f, q = 0.f;
#pragma unroll
    for (int c = 0; c < 4; ++c) {
        s += v[c].x + v[c].y + v[c].z + v[c].w;
        q += v[c].x * v[c].x + v[c].y * v[c].y
           + v[c].z * v[c].z + v[c].w * v[c].w;
    }
#pragma unroll
    for (int off = 16; off > 0; off >>= 1) {
        s += __shfl_xor_sync(0xffffffffu, s, off);
        q += __shfl_xor_sync(0xffffffffu, q, off);
    }

    const float mean = s * (1.0f / 512.0f);
    const float var  = q * (1.0f / 512.0f) - mean * mean;
    const float rstd = rsqrtf(var + 1e-5f);

#pragma unroll
    for (int c = 0; c < 4; ++c) {
        int col = c * 128 + lane * 4;
        float4 g = *(const float4*)&gam[col];
        float4 be = *(const float4*)&bet[col];
        float4 y;
        y.x = (v[c].x - mean) * rstd * g.x + be.x;
        y.y = (v[c].y - mean) * rstd * g.y + be.y;
        y.z = (v[c].z - mean) * rstd * g.z + be.z;
        y.w = (v[c].w - mean) * rstd * g.w + be.w;
        *(float4*)&out[base + col] = y;
        if (outh) {
            uint32_t h0, h1, l0, l1;
            split2(y.x, y.y, h0, l0);
            split2(y.z, y.w, h1, l1);
            *(uint2*)&outh[base + col] = make_uint2(h0, h1);
            *(uint2*)&outl[base + col] = make_uint2(l0, l1);
        }
    }
}

// ---------------------------------------------------------------------------
// Fused splitter: 8 segments of fp32 -> fp16 hi/lo (one launch).
// ---------------------------------------------------------------------------
struct SplitArgs {
    const float* src[8];
    f16* dh[8];
    f16* dl[8];
    int bstart[9];
};

__global__ void fused_split_kernel(SplitArgs sa)
{
    int blk = blockIdx.x;
    int seg = 0;
#pragma unroll
    for (int s = 1; s < 8; ++s) seg += (blk >= sa.bstart[s]);
    int idx = (blk - sa.bstart[seg]) * 256 + threadIdx.x;
    float4 x = ((const float4*)sa.src[seg])[idx];
    uint32_t h0, h1, l0, l1;
    split2(x.x, x.y, h0, l0);
    split2(x.z, x.w, h1, l1);
    ((uint2*)sa.dh[seg])[idx] = make_uint2(h0, h1);
    ((uint2*)sa.dl[seg])[idx] = make_uint2(l0, l1);
}

// ---------------------------------------------------------------------------
extern "C" void kernel_launch(void* const* d_in, const int* in_sizes, int n_in,
                              void* d_out, int out_size)
{
    const float* x   = (const float*)d_in[0];
    const float* aiw = (const float*)d_in[1];
    const float* aib = (const float*)d_in[2];
    const float* aow = (const float*)d_in[3];
    const float* aob = (const float*)d_in[4];
    const float* l1w = (const float*)d_in[5];
    const float* l1b = (const float*)d_in[6];
    const float* l2w = (const float*)d_in[7];
    const float* l2b = (const float*)d_in[8];
    const float* f1w = (const float*)d_in[9];
    const float* f1b = (const float*)d_in[10];
    const float* f2w = (const float*)d_in[11];
    const float* f2b = (const float*)d_in[12];
    const float* flw = (const float*)d_in[13];
    const float* flb = (const float*)d_in[14];
    const float* w0  = (const float*)d_in[15];
    const float* b0  = (const float*)d_in[16];
    const float* w1  = (const float*)d_in[17];
    const float* b1  = (const float*)d_in[18];
    const float* w2  = (const float*)d_in[19];
    const float* b2  = (const float*)d_in[20];
    float* out = (float*)d_out;

    f16 *wh, *wl, *s0h, *s0l, *s1h, *s1l;
    float *h, *qkv, *part;
    cudaGetSymbolAddress((void**)&wh,   g_wh);
    cudaGetSymbolAddress((void**)&wl,   g_wl);
    cudaGetSymbolAddress((void**)&s0h,  g_s0h);
    cudaGetSymbolAddress((void**)&s0l,  g_s0l);
    cudaGetSymbolAddress((void**)&s1h,  g_s1h);
    cudaGetSymbolAddress((void**)&s1l,  g_s1l);
    cudaGetSymbolAddress((void**)&h,    g_h);
    cudaGetSymbolAddress((void**)&qkv,  g_qkv);
    cudaGetSymbolAddress((void**)&part, g_part);

    cudaFuncSetAttribute(gemm_f16_kernel,
                         cudaFuncAttributeMaxDynamicSharedMemorySize, GEMM_SMEM);
    cudaFuncSetAttribute(final_tc_kernel,
                         cudaFuncAttributeMaxDynamicSharedMemorySize, REL_SMEM);

    // ---- launch 1: all splits fused (weights + x) ----
    {
        SplitArgs sa;
        sa.src[0] = aiw; sa.dh[0] = wh + OFF_AIW; sa.dl[0] = wl + OFF_AIW;
        sa.src[1] = aow; sa.dh[1] = wh + OFF_AOW; sa.dl[1] = wl + OFF_AOW;
        sa.src[2] = f1w; sa.dh[2] = wh + OFF_F1W; sa.dl[2] = wl + OFF_F1W;
        sa.src[3] = f2w; sa.dh[3] = wh + OFF_F2W; sa.dl[3] = wl + OFF_F2W;
        sa.src[4] = w0;  sa.dh[4] = wh + OFF_W0;  sa.dl[4] = wl + OFF_W0;
        sa.src[5] = w1;  sa.dh[5] = wh + OFF_W1;  sa.dl[5] = wl + OFF_W1;
        sa.src[6] = w2;  sa.dh[6] = wh + OFF_W2;  sa.dl[6] = wl + OFF_W2;
        sa.src[7] = x;   sa.dh[7] = s0h;          sa.dl[7] = s0l;
        int sizes[8] = {2359296, 786432, 3145728, 3145728,
                        1048576, 1048576, 1048576, 524288};
        int acc = 0;
        for (int s = 0; s < 8; ++s) { sa.bstart[s] = acc; acc += sizes[s] / 1024; }
        sa.bstart[8] = acc;
        fused_split_kernel<<<acc, 256>>>(sa);
    }

    // ---- encoder: 3 post-norm layers ----
    for (int i = 0; i < 3; ++i) {
        // qkv: grid (24,16,1)=384 CTAs, 16 chunks each
        gemm_f16_kernel<<<dim3(24, 16, 1), 128, GEMM_SMEM>>>(
            s0h, s0l, wh + OFF_AIW + (size_t)i * 786432, wl + OFF_AIW + (size_t)i * 786432,
            aib + i * 1536, qkv, nullptr, nullptr, 1536, 512, 0, 1, 0, -1, 0, 0, 0, 0);

        attn_kernel<<<dim3(SS, HH), 64>>>(qkv, s1h, s1l);

        // attn-out, split-K4 (ncu slot 4 on i=0): grid (8,16,4)=512
        gemm_f16_kernel<<<dim3(8, 16, 4), 128, GEMM_SMEM>>>(
            s1h, s1l, wh + OFF_AOW + (size_t)i * 262144, wl + OFF_AOW + (size_t)i * 262144,
            aob + i * 512, part, nullptr, nullptr, 512, 512, 0, 4, PSTR, -1, 0, 0, 0, 0);

        add_ln_kernel<<<NT / 8, 256>>>((i == 0) ? x : h, part, 4, PSTR,
                                       l1w + i * 512, l1b + i * 512, h, s0h, s0l);

        // ff1 = relu(...) -> fp16 splits : grid (32,16)=512
        gemm_f16_kernel<<<dim3(32, 16, 1), 128, GEMM_SMEM>>>(
            s0h, s0l, wh + OFF_F1W + (size_t)i * 1048576, wl + OFF_F1W + (size_t)i * 1048576,
            f1b + i * 2048, nullptr, s1h, s1l, 2048, 512, 1, 1, 0, -1, 0, 0, 0, 0);

        // ff2, split-K4 : grid (8,16,4)=512, 16 chunks
        gemm_f16_kernel<<<dim3(8, 16, 4), 128, GEMM_SMEM>>>(
            s1h, s1l, wh + OFF_F2W + (size_t)i * 1048576, wl + OFF_F2W + (size_t)i * 1048576,
            f2b + i * 512, part, nullptr, nullptr, 512, 2048, 0, 4, PSTR, -1, 0, 0, 0, 0);

        add_ln_kernel<<<NT / 8, 256>>>(h, part, 4, PSTR,
                                       l2w + i * 512, l2b + i * 512, h, s0h, s0l);
    }

    // final encoder LN
    add_ln_kernel<<<NT / 8, 256>>>(h, (const float*)nullptr, 0, 0,
                                   flw, flb, h, s0h, s0l);

    // ---- 4 projection MLPs, batched via blockIdx.z ----
    const int ZW = 262144, ZB = 512, ZC = NT * DD;
    gemm_f16_kernel<<<dim3(8, 16, 4), 128, GEMM_SMEM>>>(
        s0h, s0l, wh + OFF_W0, wl + OFF_W0, b0, nullptr, s1h, s1l,
        512, 512, 1, 1, 0, -1, 0, ZW, ZB, ZC);
    gemm_f16_kernel<<<dim3(8, 16, 4), 128, GEMM_SMEM>>>(
        s1h, s1l, wh + OFF_W1, wl + OFF_W1, b1, nullptr, s0h, s0l,
        512, 512, 1, 1, 0, -1, ZC, ZW, ZB, ZC);
    // mlp2: 4 z-batched fp32 outputs -> part slabs [sub|obj|vsub|vobj];
    // z==1 (obj) additionally writes fp16-hi to s1h (fused obj split)
    gemm_f16_kernel<<<dim3(8, 16, 4), 128, GEMM_SMEM>>>(
        s0h, s0l, wh + OFF_W2, wl + OFF_W2, b2, part, s1h, nullptr,
        512, 512, 0, 1, 0, 1, ZC, ZW, ZB, PSTR);

    // relation tensor: (8, 128, 128, 128), single-term fp16, fused Wv
    final_tc_kernel<<<dim3(SS, LL), 256, REL_SMEM>>>(
        part, s1h, part + (size_t)2 * PSTR, part + (size_t)3 * PSTR, out);
}

// round 15
// speedup vs baseline: 1.0189x; 1.0189x over previous
#include <cuda_runtime.h>
#include <cuda_fp16.h>
#include <math.h>
#include <stdint.h>

// ---------------------------------------------------------------------------
// GraphDecoder on tensor cores (mma.sync fp16, hi/lo split, fp32 acc).
// Round 15 = R12 baseline (398.2us, best measured) + fused Wv ONLY:
//  - relation kernel computes W_bi = vsub*vobj in its ws prologue
//    (deletes the g_Wv global pass; mul_split becomes obj-split only)
//  - everything else identical to R12 (block add_ln, qkv ks=1,
//    separate obj_split kernel, 17-arg GEMM)
// ---------------------------------------------------------------------------

#define LL  8
#define SS  128
#define DD  512
#define HH  8
#define HDD 64
#define NT  1024

typedef __half f16;

// ---- persistent scratch ----------------------------------------------------
#define OFF_AIW 0            // 3 x 786432
#define OFF_AOW 2359296      // 3 x 262144
#define OFF_F1W 3145728      // 3 x 1048576
#define OFF_F2W 6291456      // 3 x 1048576
#define OFF_W0  9437184      // 4 x 262144
#define OFF_W1  10485760
#define OFF_W2  11534336
#define WTOT    12582912

#define PSTR  (NT * DD)           // 524288 floats per partial slab

__device__ f16   g_wh[WTOT], g_wl[WTOT];
__device__ f16   g_s0h[4 * NT * DD], g_s0l[4 * NT * DD];
__device__ f16   g_s1h[4 * NT * DD], g_s1l[4 * NT * DD];
__device__ float g_h[NT * DD];
__device__ float g_qkv[NT * 3 * DD];
__device__ float g_part[8 * NT * DD];      // split-K / batch partial arena

// ========================= low-level helpers ================================
__device__ __forceinline__ uint32_t smem_u32(const void* p) {
    uint32_t a;
    asm("{ .reg .u64 t; cvta.to.shared.u64 t, %1; cvt.u32.u64 %0, t; }"
        : "=r"(a) : "l"(p));
    return a;
}

// swizzle for 64-byte rows: XOR bits [4:6) with bits [7:9)
__device__ __forceinline__ uint32_t swz(uint32_t off) {
    return off ^ (((off >> 7) & 3u) << 4);
}

__device__ __forceinline__ void ldmx4(uint32_t* r, uint32_t addr) {
    asm volatile("ldmatrix.sync.aligned.m8n8.x4.shared.b16 {%0,%1,%2,%3}, [%4];"
        : "=r"(r[0]), "=r"(r[1]), "=r"(r[2]), "=r"(r[3]) : "r"(addr));
}

__device__ __forceinline__ void mma16816(float* d, const uint32_t* a,
                                         const uint32_t* b) {
    asm volatile(
        "mma.sync.aligned.m16n8k16.row.col.f32.f16.f16.f32 "
        "{%0,%1,%2,%3}, {%4,%5,%6,%7}, {%8,%9}, {%0,%1,%2,%3};"
        : "+f"(d[0]), "+f"(d[1]), "+f"(d[2]), "+f"(d[3])
        : "r"(a[0]), "r"(a[1]), "r"(a[2]), "r"(a[3]), "r"(b[0]), "r"(b[1]));
}

__device__ __forceinline__ void cp16(uint32_t smem, const void* g) {
    asm volatile("cp.async.cg.shared.global [%0], [%1], 16;"
        :: "r"(smem), "l"(g));
}
#define CP_COMMIT asm volatile("cp.async.commit_group;" ::: "memory")
#define CP_WAIT1  asm volatile("cp.async.wait_group 1;" ::: "memory")
#define CP_WAIT2  asm volatile("cp.async.wait_group 2;" ::: "memory")

__device__ __forceinline__ void split2(float x, float y, uint32_t& hi, uint32_t& lo) {
    __half2 h, l;
    h.x = __float2half(x); h.y = __float2half(y);
    l.x = __float2half(x - __half2float(h.x));
    l.y = __float2half(y - __half2float(h.y));
    hi = *(uint32_t*)&h; lo = *(uint32_t*)&l;
}

__device__ __forceinline__ uint32_t pack2(float x, float y) {
    __half2 h;
    h.x = __float2half(x); h.y = __float2half(y);
    return *(uint32_t*)&h;
}

#define TILE_B  8192   // 128x32 f16 tile
#define TILE64  4096   // 64x32 f16 tile

// ---------------------------------------------------------------------------
// GEMM tile-mma (64x64, 4 warps 2m x 2n): A both-kk prefetch, term-outermost.
// ---------------------------------------------------------------------------
__device__ __forceinline__ void tile_mma44(
    uint32_t ahB, uint32_t alB, uint32_t bhB, uint32_t blB,
    const uint32_t* a0, const uint32_t* a1, const uint32_t (*bo)[2],
    float (&acc)[2][4][4])
{
    uint32_t ah[2][2][4], al[2][2][4];   // [kk][mt][4]
#pragma unroll
    for (int kk = 0; kk < 2; ++kk) {
        ldmx4(ah[kk][0], ahB + a0[kk]);
        ldmx4(ah[kk][1], ahB + a1[kk]);
        ldmx4(al[kk][0], alB + a0[kk]);
        ldmx4(al[kk][1], alB + a1[kk]);
    }
#pragma unroll
    for (int kk = 0; kk < 2; ++kk) {
        uint32_t bh[4][2], bl[4][2];
#pragma unroll
        for (int ng = 0; ng < 2; ++ng) {
            uint32_t r[4];
            ldmx4(r, bhB + bo[ng][kk]);
            bh[2*ng][0] = r[0]; bh[2*ng][1] = r[1];
            bh[2*ng+1][0] = r[2]; bh[2*ng+1][1] = r[3];
            ldmx4(r, blB + bo[ng][kk]);
            bl[2*ng][0] = r[0]; bl[2*ng][1] = r[1];
            bl[2*ng+1][0] = r[2]; bl[2*ng+1][1] = r[3];
        }
#pragma unroll
        for (int mt = 0; mt < 2; ++mt)
#pragma unroll
            for (int nt = 0; nt < 4; ++nt)
                mma16816(acc[mt][nt], ah[kk][mt], bh[nt]);
#pragma unroll
        for (int mt = 0; mt < 2; ++mt)
#pragma unroll
            for (int nt = 0; nt < 4; ++nt)
                mma16816(acc[mt][nt], ah[kk][mt], bl[nt]);
#pragma unroll
        for (int mt = 0; mt < 2; ++mt)
#pragma unroll
            for (int nt = 0; nt < 4; ++nt)
                mma16816(acc[mt][nt], al[kk][mt], bh[nt]);
    }
}

// ---------------------------------------------------------------------------
// Relation tile-mma (128x128, SINGLE term): acc[2][8][4].
// ---------------------------------------------------------------------------
__device__ __forceinline__ void tile_mma_rel(
    uint32_t ahB, uint32_t bhB,
    const uint32_t* a0, const uint32_t* a1, const uint32_t (*bo)[2],
    float (&acc)[2][8][4])
{
#pragma unroll
    for (int kk = 0; kk < 2; ++kk) {
        uint32_t ah[2][4];
        ldmx4(ah[0], ahB + a0[kk]);
        ldmx4(ah[1], ahB + a1[kk]);
#pragma unroll
        for (int hf = 0; hf < 2; ++hf) {
            uint32_t bh[4][2];
#pragma unroll
            for (int ng = 0; ng < 2; ++ng) {
                uint32_t r[4];
                ldmx4(r, bhB + bo[2 * hf + ng][kk]);
                bh[2*ng][0] = r[0]; bh[2*ng][1] = r[1];
                bh[2*ng+1][0] = r[2]; bh[2*ng+1][1] = r[3];
            }
#pragma unroll
            for (int mt = 0; mt < 2; ++mt)
#pragma unroll
                for (int nt = 0; nt < 4; ++nt)
                    mma16816(acc[mt][4*hf + nt], ah[mt], bh[nt]);
        }
    }
}

// ---------------------------------------------------------------------------
// f16 GEMM (3-term), batched (z) + split-K (ks).
// 64x64 tile, 128 threads, BK=32, 3-stage ring, ONE sync/chunk, 4 CTAs/SM.
// ---------------------------------------------------------------------------
#define G_AH 0
#define G_AL 4096
#define G_BH 8192
#define G_BL 12288
#define STAGE_BYTES 16384
#define GEMM_SMEM   (3 * STAGE_BYTES + 128)   // 49280

__global__ void __launch_bounds__(128, 4) gemm_f16_kernel(
    const f16* __restrict__ Ah, const f16* __restrict__ Al,
    const f16* __restrict__ Wh, const f16* __restrict__ Wl,
    const float* __restrict__ bias,
    float* __restrict__ Cf, f16* __restrict__ Ch, f16* __restrict__ Cl,
    int N, int K, int relu, int ks, int pstr,
    int zsA, int zsW, int zsB, int zsC)
{
    extern __shared__ char smch[];
    const uint32_t base = (smem_u32(smch) + 127) & ~127u;

    const int z  = blockIdx.z / ks;
    const int kz = blockIdx.z % ks;
    const int Klocal = K / ks;
    const int kbase = kz * Klocal;

    Ah += (size_t)z * zsA;  Al += (size_t)z * zsA;
    Wh += (size_t)z * zsW;  Wl += (size_t)z * zsW;
    bias += (size_t)z * zsB;
    if (Cf) Cf += (size_t)z * zsC + (size_t)kz * pstr;
    if (Ch) { Ch += (size_t)z * zsC; Cl += (size_t)z * zsC; }

    const int tid  = threadIdx.x;
    const int lane = tid & 31;
    const int wid  = tid >> 5;
    const int wm   = wid & 1;
    const int wn   = wid >> 1;
    const int m0 = blockIdx.y * 64;
    const int n0 = blockIdx.x * 64;

    const f16* gsrc[8];
    uint32_t sdst[8];
#pragma unroll
    for (int it = 0; it < 8; ++it) {
        int c = tid + it * 128;
        int a = c >> 8;
        int idx = c & 255;
        int row = idx >> 2;
        int q   = idx & 3;
        const f16* p;
        if (a == 0)      p = Ah + (size_t)(m0 + row) * K;
        else if (a == 1) p = Al + (size_t)(m0 + row) * K;
        else if (a == 2) p = Wh + (size_t)(n0 + row) * K;
        else             p = Wl + (size_t)(n0 + row) * K;
        gsrc[it] = p + kbase + q * 8;
        sdst[it] = a * TILE64 + swz(row * 64 + q * 16);
    }

    const int nch = Klocal >> 5;
    auto issue = [&](int s) {
        uint32_t st = base + (s % 3) * STAGE_BYTES;
#pragma unroll
        for (int it = 0; it < 8; ++it)
            cp16(st + sdst[it], gsrc[it] + s * 32);
    };
    issue(0); CP_COMMIT;
    issue(1); CP_COMMIT;

    const int aRow = wm * 32 + (lane & 15);
    const int aCol = (lane >> 4) * 8;
    const int bRow = wn * 32 + (lane & 7) + ((lane >> 4) << 3);
    const int bCol = ((lane >> 3) & 1) * 8;
    uint32_t a0[2], a1[2], bo[2][2];
#pragma unroll
    for (int kk = 0; kk < 2; ++kk) {
        a0[kk] = swz(aRow * 64 + aCol * 2 + kk * 32);
        a1[kk] = swz((aRow + 16) * 64 + aCol * 2 + kk * 32);
#pragma unroll
        for (int ng = 0; ng < 2; ++ng)
            bo[ng][kk] = swz((bRow + ng * 16) * 64 + bCol * 2 + kk * 32);
    }

    float acc[2][4][4] = {};

    for (int s = 0; s < nch; ++s) {
        CP_WAIT1;
        __syncthreads();
        if (s + 2 < nch) issue(s + 2);
        CP_COMMIT;
        uint32_t st = base + (s % 3) * STAGE_BYTES;
        tile_mma44(st + G_AH, st + G_AL, st + G_BH, st + G_BL,
                   a0, a1, bo, acc);
    }

    const int addb = (kz == 0);
#pragma unroll
    for (int mt = 0; mt < 2; ++mt) {
        int r0 = m0 + wm * 32 + mt * 16 + (lane >> 2);
#pragma unroll
        for (int nt = 0; nt < 4; ++nt) {
            int col = n0 + wn * 32 + nt * 8 + (lane & 3) * 2;
            float b0 = addb ? bias[col] : 0.f, b1 = addb ? bias[col + 1] : 0.f;
            float v0 = acc[mt][nt][0] + b0, v1 = acc[mt][nt][1] + b1;
            float v2 = acc[mt][nt][2] + b0, v3 = acc[mt][nt][3] + b1;
            if (relu) {
                v0 = fmaxf(v0, 0.f); v1 = fmaxf(v1, 0.f);
                v2 = fmaxf(v2, 0.f); v3 = fmaxf(v3, 0.f);
            }
            if (Ch) {
                uint32_t hh, ll;
                split2(v0, v1, hh, ll);
                *(uint32_t*)&Ch[(size_t)r0 * N + col] = hh;
                *(uint32_t*)&Cl[(size_t)r0 * N + col] = ll;
                split2(v2, v3, hh, ll);
                *(uint32_t*)&Ch[(size_t)(r0 + 8) * N + col] = hh;
                *(uint32_t*)&Cl[(size_t)(r0 + 8) * N + col] = ll;
            } else {
                *(float2*)&Cf[(size_t)r0 * N + col]       = make_float2(v0, v1);
                *(float2*)&Cf[(size_t)(r0 + 8) * N + col] = make_float2(v2, v3);
            }
        }
    }
}

// ---------------------------------------------------------------------------
// Relation tensor (single-term fp16): out[b,i,:,:] = ((sub_b * W_bi) @ obj_b^T)
// W_bi = vsub[b,i,:] * vobj[b,i,:] computed in the ws prologue (fused Wv).
// A: fp32 load+scale -> fp16 (register double buffer); B: 3-stage cp.async.
// ---------------------------------------------------------------------------
#define RA_STAGE TILE_B     // Ah only
#define RB_STAGE TILE_B     // Bh only
#define REL_SMEM (2048 + 2 * RA_STAGE + 3 * RB_STAGE + 128)  // 43136

__global__ void __launch_bounds__(256, 2) final_tc_kernel(
    const float* __restrict__ sub, const f16* __restrict__ objh,
    const float* __restrict__ vsub, const float* __restrict__ vobj,
    float* __restrict__ out)
{
    extern __shared__ char smch[];
    const uint32_t sb = (smem_u32(smch) + 127) & ~127u;
    float* ws = (float*)(smch + (sb - smem_u32(smch)));
    char* aPtr = (char*)ws + 2048;
    const uint32_t aBase = sb + 2048;
    const uint32_t bBase = aBase + 2 * RA_STAGE;

    const int i = blockIdx.x;
    const int b = blockIdx.y;
    const int tid  = threadIdx.x;
    const int lane = tid & 31;
    const int wid  = tid >> 5;
    const int wm   = wid & 3;
    const int wn   = wid >> 2;

    // W row = vsub * vobj (fused; removes the g_Wv global pass)
    {
        const size_t rb = (size_t)(b * SS + i) * DD;
        float2 a0v = *(const float2*)&vsub[rb + 2 * tid];
        float2 b0v = *(const float2*)&vobj[rb + 2 * tid];
        ws[2 * tid]     = a0v.x * b0v.x;
        ws[2 * tid + 1] = a0v.y * b0v.y;
    }

    const float* subB = sub + (size_t)b * SS * DD;
    const f16* ohB = objh + (size_t)b * SS * DD;

    const f16* bsrc[2];
    uint32_t bdst[2];
#pragma unroll
    for (int it = 0; it < 2; ++it) {
        int c = tid + it * 256;
        int row = c >> 2, q = c & 3;
        bsrc[it] = ohB + (size_t)row * DD + q * 8;
        bdst[it] = swz(row * 64 + q * 16);
    }
    int aLrow[4], aLc4[4];
#pragma unroll
    for (int it = 0; it < 4; ++it) {
        int idx = tid + it * 256;
        aLrow[it] = idx >> 3;
        aLc4[it]  = (idx & 7) << 2;
    }

    auto issueB = [&](int s) {
        uint32_t st = bBase + (s % 3) * RB_STAGE;
#pragma unroll
        for (int it = 0; it < 2; ++it)
            cp16(st + bdst[it], bsrc[it] + s * 32);
    };
    auto loadA = [&](int s, float4* r) {
#pragma unroll
        for (int it = 0; it < 4; ++it)
            r[it] = *(const float4*)&subB[(size_t)aLrow[it] * DD + s * 32 + aLc4[it]];
    };
    auto storeA = [&](int s, const float4* r) {
        char* dh = aPtr + (s & 1) * RA_STAGE;
        int kc = s * 32;
#pragma unroll
        for (int it = 0; it < 4; ++it) {
            float4 v = r[it];
            v.x *= ws[kc + aLc4[it]];     v.y *= ws[kc + aLc4[it] + 1];
            v.z *= ws[kc + aLc4[it] + 2]; v.w *= ws[kc + aLc4[it] + 3];
            uint32_t h0 = pack2(v.x, v.y);
            uint32_t h1 = pack2(v.z, v.w);
            uint32_t off = swz(aLrow[it] * 64 + aLc4[it] * 2);
            *(uint2*)(dh + off) = make_uint2(h0, h1);
        }
    };

    issueB(0); CP_COMMIT;
    issueB(1); CP_COMMIT;
    issueB(2); CP_COMMIT;
    __syncthreads();              // ws visible
    {
        float4 r0[4];
        loadA(0, r0);
        storeA(0, r0);
    }

    const int aRow = wm * 32 + (lane & 15);
    const int aCol = (lane >> 4) * 8;
    const int bRow = wn * 64 + (lane & 7) + ((lane >> 4) << 3);
    const int bCol = ((lane >> 3) & 1) * 8;
    uint32_t a0[2], a1[2], bo[4][2];
#pragma unroll
    for (int kk = 0; kk < 2; ++kk) {
        a0[kk] = swz(aRow * 64 + aCol * 2 + kk * 32);
        a1[kk] = swz((aRow + 16) * 64 + aCol * 2 + kk * 32);
#pragma unroll
        for (int ng = 0; ng < 4; ++ng)
            bo[ng][kk] = swz((bRow + ng * 16) * 64 + bCol * 2 + kk * 32);
    }

    float acc[2][8][4] = {};
    float4 pre[4];

    for (int s = 0; s < 16; ++s) {
        if (s + 1 < 16) loadA(s + 1, pre);
        CP_WAIT2;
        __syncthreads();
        uint32_t aB = aBase + (s & 1) * RA_STAGE;
        uint32_t bB = bBase + (s % 3) * RB_STAGE;
        tile_mma_rel(aB, bB, a0, a1, bo, acc);
        __syncthreads();
        if (s + 1 < 16) storeA(s + 1, pre);
        if (s + 3 < 16) issueB(s + 3);
        CP_COMMIT;
    }

    float* outB = out + (size_t)(b * SS + i) * SS * SS;
#pragma unroll
    for (int mt = 0; mt < 2; ++mt) {
        int r0 = wm * 32 + mt * 16 + (lane >> 2);
#pragma unroll
        for (int nt = 0; nt < 8; ++nt) {
            int col = wn * 64 + nt * 8 + (lane & 3) * 2;
            *(float2*)&outB[(size_t)r0 * SS + col] =
                make_float2(acc[mt][nt][0], acc[mt][nt][1]);
            *(float2*)&outB[(size_t)(r0 + 8) * SS + col] =
                make_float2(acc[mt][nt][2], acc[mt][nt][3]);
        }
    }
}

// ---------------------------------------------------------------------------
// Attention over axis L per (s, h); single qkv buffer; fp16 hi/lo out.
// ---------------------------------------------------------------------------
__global__ void attn_kernel(const float* __restrict__ qkv,
                            f16* __restrict__ oh, f16* __restrict__ ol)
{
    const int s = blockIdx.x;
    const int h = blockIdx.y;
    const int t = threadIdx.x;  // 0..63

    __shared__ float qs[8][65], ks[8][65], vs[8][65];
    __shared__ float at[8][9];

#pragma unroll
    for (int l = 0; l < 8; ++l) {
        size_t base = (size_t)(l * SS + s) * (3 * DD) + h * HDD + t;
        qs[l][t] = qkv[base];
        ks[l][t] = qkv[base + DD];
        vs[l][t] = qkv[base + 2 * DD];
    }
    __syncthreads();

    const int l = t >> 3;
    const int m = t & 7;
    float sc = 0.0f;
#pragma unroll
    for (int d = 0; d < HDD; ++d) sc += qs[l][d] * ks[m][d];
    sc *= 0.125f;

    float mx = sc;
#pragma unroll
    for (int off = 1; off < 8; off <<= 1)
        mx = fmaxf(mx, __shfl_xor_sync(0xffffffffu, mx, off));
    float e = __expf(sc - mx);
    float sm = e;
#pragma unroll
    for (int off = 1; off < 8; off <<= 1)
        sm += __shfl_xor_sync(0xffffffffu, sm, off);
    at[l][m] = e / sm;
    __syncthreads();

    const int dg = (t & 7) * 8;
    float accv[8] = {};
#pragma unroll
    for (int mm = 0; mm < 8; ++mm) {
        float a = at[l][mm];
#pragma unroll
        for (int j = 0; j < 8; ++j)
            accv[j] = fmaf(a, vs[mm][dg + j], accv[j]);
    }
    size_t ob = (size_t)(l * SS + s) * DD + h * HDD + dg;
#pragma unroll
    for (int j = 0; j < 8; j += 2) {
        uint32_t hh, ll;
        split2(accv[j], accv[j + 1], hh, ll);
        *(uint32_t*)&oh[ob + j] = hh;
        *(uint32_t*)&ol[ob + j] = ll;
    }
}

// ---------------------------------------------------------------------------
// out = LayerNorm(a + sum_{p<np} P[p*pstr + .]); emits fp16 hi/lo if outh.
// (R12 block-reduction version — measured fastest configuration.)
// ---------------------------------------------------------------------------
__global__ void add_ln_kernel(const float* __restrict__ a,
                              const float* __restrict__ P, int np, int pstr,
                              const float* __restrict__ gam, const float* __restrict__ bet,
                              float* __restrict__ out,
                              f16* __restrict__ outh, f16* __restrict__ outl)
{
    const int row = blockIdx.x;
    const int t = threadIdx.x;
    const size_t base = (size_t)row * DD;
    const int c = 2 * t;

    float v0 = a[base + c];
    float v1 = a[base + c + 1];
    for (int p = 0; p < np; ++p) {
        v0 += P[(size_t)p * pstr + base + c];
        v1 += P[(size_t)p * pstr + base + c + 1];
    }

    float s = v0 + v1;
    float q = v0 * v0 + v1 * v1;

    __shared__ float sred[16];
#pragma unroll
    for (int off = 16; off > 0; off >>= 1) {
        s += __shfl_xor_sync(0xffffffffu, s, off);
        q += __shfl_xor_sync(0xffffffffu, q, off);
    }
    if ((t & 31) == 0) { sred[t >> 5] = s; sred[(t >> 5) + 8] = q; }
    __syncthreads();
    if (t < 32) {
        float ss = (t < 8) ? sred[t] : 0.0f;
        float qq = (t < 8) ? sred[t + 8] : 0.0f;
#pragma unroll
        for (int off = 4; off > 0; off >>= 1) {
            ss += __shfl_xor_sync(0xffffffffu, ss, off);
            qq += __shfl_xor_sync(0xffffffffu, qq, off);
        }
        if (t == 0) { sred[0] = ss; sred[1] = qq; }
    }
    __syncthreads();

    const float mean = sred[0] * (1.0f / 512.0f);
    const float var  = sred[1] * (1.0f / 512.0f) - mean * mean;
    const float rstd = rsqrtf(var + 1e-5f);

    float y0 = (v0 - mean) * rstd * gam[c]     + bet[c];
    float y1 = (v1 - mean) * rstd * gam[c + 1] + bet[c + 1];
    *(float2*)&out[base + c] = make_float2(y0, y1);
    if (outh) {
        uint32_t hh, ll;
        split2(y0, y1, hh, ll);
        *(uint32_t*)&outh[base + c] = hh;
        *(uint32_t*)&outl[base + c] = ll;
    }
}

// ---------------------------------------------------------------------------
// Fused splitter: 8 segments of fp32 -> fp16 hi/lo (one launch).
// ---------------------------------------------------------------------------
struct SplitArgs {
    const float* src[8];
    f16* dh[8];
    f16* dl[8];
    int bstart[9];
};

__global__ void fused_split_kernel(SplitArgs sa)
{
    int blk = blockIdx.x;
    int seg = 0;
#pragma unroll
    for (int s = 1; s < 8; ++s) seg += (blk >= sa.bstart[s]);
    int idx = (blk - sa.bstart[seg]) * 256 + threadIdx.x;
    float4 x = ((const float4*)sa.src[seg])[idx];
    uint32_t h0, h1, l0, l1;
    split2(x.x, x.y, h0, l0);
    split2(x.z, x.w, h1, l1);
    ((uint2*)sa.dh[seg])[idx] = make_uint2(h0, h1);
    ((uint2*)sa.dl[seg])[idx] = make_uint2(l0, l1);
}

// ---------------------------------------------------------------------------
// obj (= P1 slab) -> fp16 (hi only).
// ---------------------------------------------------------------------------
__global__ void obj_split_kernel(const float* __restrict__ P,
                                 f16* __restrict__ oh)
{
    int i = blockIdx.x * blockDim.x + threadIdx.x;   // float4 index
    float4 o = ((const float4*)P)[i + PSTR / 4];
    ((uint2*)oh)[i] = make_uint2(pack2(o.x, o.y), pack2(o.z, o.w));
}

// ---------------------------------------------------------------------------
extern "C" void kernel_launch(void* const* d_in, const int* in_sizes, int n_in,
                              void* d_out, int out_size)
{
    const float* x   = (const float*)d_in[0];
    const float* aiw = (const float*)d_in[1];
    const float* aib = (const float*)d_in[2];
    const float* aow = (const float*)d_in[3];
    const float* aob = (const float*)d_in[4];
    const float* l1w = (const float*)d_in[5];
    const float* l1b = (const float*)d_in[6];
    const float* l2w = (const float*)d_in[7];
    const float* l2b = (const float*)d_in[8];
    const float* f1w = (const float*)d_in[9];
    const float* f1b = (const float*)d_in[10];
    const float* f2w = (const float*)d_in[11];
    const float* f2b = (const float*)d_in[12];
    const float* flw = (const float*)d_in[13];
    const float* flb = (const float*)d_in[14];
    const float* w0  = (const float*)d_in[15];
    const float* b0  = (const float*)d_in[16];
    const float* w1  = (const float*)d_in[17];
    const float* b1  = (const float*)d_in[18];
    const float* w2  = (const float*)d_in[19];
    const float* b2  = (const float*)d_in[20];
    float* out = (float*)d_out;

    f16 *wh, *wl, *s0h, *s0l, *s1h, *s1l;
    float *h, *qkv, *part;
    cudaGetSymbolAddress((void**)&wh,   g_wh);
    cudaGetSymbolAddress((void**)&wl,   g_wl);
    cudaGetSymbolAddress((void**)&s0h,  g_s0h);
    cudaGetSymbolAddress((void**)&s0l,  g_s0l);
    cudaGetSymbolAddress((void**)&s1h,  g_s1h);
    cudaGetSymbolAddress((void**)&s1l,  g_s1l);
    cudaGetSymbolAddress((void**)&h,    g_h);
    cudaGetSymbolAddress((void**)&qkv,  g_qkv);
    cudaGetSymbolAddress((void**)&part, g_part);

    cudaFuncSetAttribute(gemm_f16_kernel,
                         cudaFuncAttributeMaxDynamicSharedMemorySize, GEMM_SMEM);
    cudaFuncSetAttribute(final_tc_kernel,
                         cudaFuncAttributeMaxDynamicSharedMemorySize, REL_SMEM);

    // ---- launch 1: all splits fused (weights + x) ----
    {
        SplitArgs sa;
        sa.src[0] = aiw; sa.dh[0] = wh + OFF_AIW; sa.dl[0] = wl + OFF_AIW;
        sa.src[1] = aow; sa.dh[1] = wh + OFF_AOW; sa.dl[1] = wl + OFF_AOW;
        sa.src[2] = f1w; sa.dh[2] = wh + OFF_F1W; sa.dl[2] = wl + OFF_F1W;
        sa.src[3] = f2w; sa.dh[3] = wh + OFF_F2W; sa.dl[3] = wl + OFF_F2W;
        sa.src[4] = w0;  sa.dh[4] = wh + OFF_W0;  sa.dl[4] = wl + OFF_W0;
        sa.src[5] = w1;  sa.dh[5] = wh + OFF_W1;  sa.dl[5] = wl + OFF_W1;
        sa.src[6] = w2;  sa.dh[6] = wh + OFF_W2;  sa.dl[6] = wl + OFF_W2;
        sa.src[7] = x;   sa.dh[7] = s0h;          sa.dl[7] = s0l;
        int sizes[8] = {2359296, 786432, 3145728, 3145728,
                        1048576, 1048576, 1048576, 524288};
        int acc = 0;
        for (int s = 0; s < 8; ++s) { sa.bstart[s] = acc; acc += sizes[s] / 1024; }
        sa.bstart[8] = acc;
        fused_split_kernel<<<acc, 256>>>(sa);
    }

    // ---- encoder: 3 post-norm layers ----
    for (int i = 0; i < 3; ++i) {
        // qkv: grid (24,16,1)=384 CTAs, 16 chunks each
        gemm_f16_kernel<<<dim3(24, 16, 1), 128, GEMM_SMEM>>>(
            s0h, s0l, wh + OFF_AIW + (size_t)i * 786432, wl + OFF_AIW + (size_t)i * 786432,
            aib + i * 1536, qkv, nullptr, nullptr, 1536, 512, 0, 1, 0, 0, 0, 0, 0);

        attn_kernel<<<dim3(SS, HH), 64>>>(qkv, s1h, s1l);

        // attn-out, split-K4: grid (8,16,4)=512
        gemm_f16_kernel<<<dim3(8, 16, 4), 128, GEMM_SMEM>>>(
            s1h, s1l, wh + OFF_AOW + (size_t)i * 262144, wl + OFF_AOW + (size_t)i * 262144,
            aob + i * 512, part, nullptr, nullptr, 512, 512, 0, 4, PSTR, 0, 0, 0, 0);

        add_ln_kernel<<<NT, 256>>>((i == 0) ? x : h, part, 4, PSTR,
                                   l1w + i * 512, l1b + i * 512, h, s0h, s0l);

        // ff1 = relu(...) -> fp16 splits : grid (32,16)=512
        gemm_f16_kernel<<<dim3(32, 16, 1), 128, GEMM_SMEM>>>(
            s0h, s0l, wh + OFF_F1W + (size_t)i * 1048576, wl + OFF_F1W + (size_t)i * 1048576,
            f1b + i * 2048, nullptr, s1h, s1l, 2048, 512, 1, 1, 0, 0, 0, 0, 0);

        // ff2, split-K4 : grid (8,16,4)=512, 16 chunks
        gemm_f16_kernel<<<dim3(8, 16, 4), 128, GEMM_SMEM>>>(
            s1h, s1l, wh + OFF_F2W + (size_t)i * 1048576, wl + OFF_F2W + (size_t)i * 1048576,
            f2b + i * 512, part, nullptr, nullptr, 512, 2048, 0, 4, PSTR, 0, 0, 0, 0);

        add_ln_kernel<<<NT, 256>>>(h, part, 4, PSTR,
                                   l2w + i * 512, l2b + i * 512, h, s0h, s0l);
    }

    // final encoder LN
    add_ln_kernel<<<NT, 256>>>(h, (const float*)nullptr, 0, 0, flw, flb, h, s0h, s0l);

    // ---- 4 projection MLPs, batched via blockIdx.z ----
    const int ZW = 262144, ZB = 512, ZC = NT * DD;
    gemm_f16_kernel<<<dim3(8, 16, 4), 128, GEMM_SMEM>>>(
        s0h, s0l, wh + OFF_W0, wl + OFF_W0, b0, nullptr, s1h, s1l,
        512, 512, 1, 1, 0, 0, ZW, ZB, ZC);
    gemm_f16_kernel<<<dim3(8, 16, 4), 128, GEMM_SMEM>>>(
        s1h, s1l, wh + OFF_W1, wl + OFF_W1, b1, nullptr, s0h, s0l,
        512, 512, 1, 1, 0, ZC, ZW, ZB, ZC);
    // mlp2: 4 z-batched fp32 outputs -> part slabs [sub|obj|vsub|vobj]
    gemm_f16_kernel<<<dim3(8, 16, 4), 128, GEMM_SMEM>>>(
        s0h, s0l, wh + OFF_W2, wl + OFF_W2, b2, part, nullptr, nullptr,
        512, 512, 0, 1, 0, ZC, ZW, ZB, PSTR);

    // obj -> fp16 (hi)
    obj_split_kernel<<<512, 256>>>(part, s1h);

    // relation tensor: (8, 128, 128, 128), single-term fp16, fused Wv
    final_tc_kernel<<<dim3(SS, LL), 256, REL_SMEM>>>(
        part, s1h, part + (size_t)2 * PSTR, part + (size_t)3 * PSTR, out);
}

// round 16
// speedup vs baseline: 1.0221x; 1.0031x over previous
#include <cuda_runtime.h>
#include <cuda_fp16.h>
#include <math.h>
#include <stdint.h>

// ---------------------------------------------------------------------------
// GraphDecoder on tensor cores (mma.sync fp16, hi/lo split, fp32 acc).
// Round 16 = R15 (best, 398us) + strictly-subtractive chain cuts:
//  - final encoder LN fused into layer-2 LN2 (double-LN add_ln mode)
//  - dead fp32 store skipped in the fused LN (out==nullptr path)
//  - attn: 128-thread blocks (2 (s,h) pairs), grid 1024 -> 512 blocks
// ---------------------------------------------------------------------------

#define LL  8
#define SS  128
#define DD  512
#define HH  8
#define HDD 64
#define NT  1024

typedef __half f16;

// ---- persistent scratch ----------------------------------------------------
#define OFF_AIW 0            // 3 x 786432
#define OFF_AOW 2359296      // 3 x 262144
#define OFF_F1W 3145728      // 3 x 1048576
#define OFF_F2W 6291456      // 3 x 1048576
#define OFF_W0  9437184      // 4 x 262144
#define OFF_W1  10485760
#define OFF_W2  11534336
#define WTOT    12582912

#define PSTR  (NT * DD)           // 524288 floats per partial slab

__device__ f16   g_wh[WTOT], g_wl[WTOT];
__device__ f16   g_s0h[4 * NT * DD], g_s0l[4 * NT * DD];
__device__ f16   g_s1h[4 * NT * DD], g_s1l[4 * NT * DD];
__device__ float g_h[NT * DD];
__device__ float g_qkv[NT * 3 * DD];
__device__ float g_part[8 * NT * DD];      // split-K / batch partial arena

// ========================= low-level helpers ================================
__device__ __forceinline__ uint32_t smem_u32(const void* p) {
    uint32_t a;
    asm("{ .reg .u64 t; cvta.to.shared.u64 t, %1; cvt.u32.u64 %0, t; }"
        : "=r"(a) : "l"(p));
    return a;
}

// swizzle for 64-byte rows: XOR bits [4:6) with bits [7:9)
__device__ __forceinline__ uint32_t swz(uint32_t off) {
    return off ^ (((off >> 7) & 3u) << 4);
}

__device__ __forceinline__ void ldmx4(uint32_t* r, uint32_t addr) {
    asm volatile("ldmatrix.sync.aligned.m8n8.x4.shared.b16 {%0,%1,%2,%3}, [%4];"
        : "=r"(r[0]), "=r"(r[1]), "=r"(r[2]), "=r"(r[3]) : "r"(addr));
}

__device__ __forceinline__ void mma16816(float* d, const uint32_t* a,
                                         const uint32_t* b) {
    asm volatile(
        "mma.sync.aligned.m16n8k16.row.col.f32.f16.f16.f32 "
        "{%0,%1,%2,%3}, {%4,%5,%6,%7}, {%8,%9}, {%0,%1,%2,%3};"
        : "+f"(d[0]), "+f"(d[1]), "+f"(d[2]), "+f"(d[3])
        : "r"(a[0]), "r"(a[1]), "r"(a[2]), "r"(a[3]), "r"(b[0]), "r"(b[1]));
}

__device__ __forceinline__ void cp16(uint32_t smem, const void* g) {
    asm volatile("cp.async.cg.shared.global [%0], [%1], 16;"
        :: "r"(smem), "l"(g));
}
#define CP_COMMIT asm volatile("cp.async.commit_group;" ::: "memory")
#define CP_WAIT1  asm volatile("cp.async.wait_group 1;" ::: "memory")
#define CP_WAIT2  asm volatile("cp.async.wait_group 2;" ::: "memory")

__device__ __forceinline__ void split2(float x, float y, uint32_t& hi, uint32_t& lo) {
    __half2 h, l;
    h.x = __float2half(x); h.y = __float2half(y);
    l.x = __float2half(x - __half2float(h.x));
    l.y = __float2half(y - __half2float(h.y));
    hi = *(uint32_t*)&h; lo = *(uint32_t*)&l;
}

__device__ __forceinline__ uint32_t pack2(float x, float y) {
    __half2 h;
    h.x = __float2half(x); h.y = __float2half(y);
    return *(uint32_t*)&h;
}

#define TILE_B  8192   // 128x32 f16 tile
#define TILE64  4096   // 64x32 f16 tile

// ---------------------------------------------------------------------------
// GEMM tile-mma (64x64, 4 warps 2m x 2n): A both-kk prefetch, term-outermost.
// ---------------------------------------------------------------------------
__device__ __forceinline__ void tile_mma44(
    uint32_t ahB, uint32_t alB, uint32_t bhB, uint32_t blB,
    const uint32_t* a0, const uint32_t* a1, const uint32_t (*bo)[2],
    float (&acc)[2][4][4])
{
    uint32_t ah[2][2][4], al[2][2][4];   // [kk][mt][4]
#pragma unroll
    for (int kk = 0; kk < 2; ++kk) {
        ldmx4(ah[kk][0], ahB + a0[kk]);
        ldmx4(ah[kk][1], ahB + a1[kk]);
        ldmx4(al[kk][0], alB + a0[kk]);
        ldmx4(al[kk][1], alB + a1[kk]);
    }
#pragma unroll
    for (int kk = 0; kk < 2; ++kk) {
        uint32_t bh[4][2], bl[4][2];
#pragma unroll
        for (int ng = 0; ng < 2; ++ng) {
            uint32_t r[4];
            ldmx4(r, bhB + bo[ng][kk]);
            bh[2*ng][0] = r[0]; bh[2*ng][1] = r[1];
            bh[2*ng+1][0] = r[2]; bh[2*ng+1][1] = r[3];
            ldmx4(r, blB + bo[ng][kk]);
            bl[2*ng][0] = r[0]; bl[2*ng][1] = r[1];
            bl[2*ng+1][0] = r[2]; bl[2*ng+1][1] = r[3];
        }
#pragma unroll
        for (int mt = 0; mt < 2; ++mt)
#pragma unroll
            for (int nt = 0; nt < 4; ++nt)
                mma16816(acc[mt][nt], ah[kk][mt], bh[nt]);
#pragma unroll
        for (int mt = 0; mt < 2; ++mt)
#pragma unroll
            for (int nt = 0; nt < 4; ++nt)
                mma16816(acc[mt][nt], ah[kk][mt], bl[nt]);
#pragma unroll
        for (int mt = 0; mt < 2; ++mt)
#pragma unroll
            for (int nt = 0; nt < 4; ++nt)
                mma16816(acc[mt][nt], al[kk][mt], bh[nt]);
    }
}

// ---------------------------------------------------------------------------
// Relation tile-mma (128x128, SINGLE term): acc[2][8][4].
// ---------------------------------------------------------------------------
__device__ __forceinline__ void tile_mma_rel(
    uint32_t ahB, uint32_t bhB,
    const uint32_t* a0, const uint32_t* a1, const uint32_t (*bo)[2],
    float (&acc)[2][8][4])
{
#pragma unroll
    for (int kk = 0; kk < 2; ++kk) {
        uint32_t ah[2][4];
        ldmx4(ah[0], ahB + a0[kk]);
        ldmx4(ah[1], ahB + a1[kk]);
#pragma unroll
        for (int hf = 0; hf < 2; ++hf) {
            uint32_t bh[4][2];
#pragma unroll
            for (int ng = 0; ng < 2; ++ng) {
                uint32_t r[4];
                ldmx4(r, bhB + bo[2 * hf + ng][kk]);
                bh[2*ng][0] = r[0]; bh[2*ng][1] = r[1];
                bh[2*ng+1][0] = r[2]; bh[2*ng+1][1] = r[3];
            }
#pragma unroll
            for (int mt = 0; mt < 2; ++mt)
#pragma unroll
                for (int nt = 0; nt < 4; ++nt)
                    mma16816(acc[mt][4*hf + nt], ah[mt], bh[nt]);
        }
    }
}

// ---------------------------------------------------------------------------
// f16 GEMM (3-term), batched (z) + split-K (ks).
// 64x64 tile, 128 threads, BK=32, 3-stage ring, ONE sync/chunk, 4 CTAs/SM.
// ---------------------------------------------------------------------------
#define G_AH 0
#define G_AL 4096
#define G_BH 8192
#define G_BL 12288
#define STAGE_BYTES 16384
#define GEMM_SMEM   (3 * STAGE_BYTES + 128)   // 49280

__global__ void __launch_bounds__(128, 4) gemm_f16_kernel(
    const f16* __restrict__ Ah, const f16* __restrict__ Al,
    const f16* __restrict__ Wh, const f16* __restrict__ Wl,
    const float* __restrict__ bias,
    float* __restrict__ Cf, f16* __restrict__ Ch, f16* __restrict__ Cl,
    int N, int K, int relu, int ks, int pstr,
    int zsA, int zsW, int zsB, int zsC)
{
    extern __shared__ char smch[];
    const uint32_t base = (smem_u32(smch) + 127) & ~127u;

    const int z  = blockIdx.z / ks;
    const int kz = blockIdx.z % ks;
    const int Klocal = K / ks;
    const int kbase = kz * Klocal;

    Ah += (size_t)z * zsA;  Al += (size_t)z * zsA;
    Wh += (size_t)z * zsW;  Wl += (size_t)z * zsW;
    bias += (size_t)z * zsB;
    if (Cf) Cf += (size_t)z * zsC + (size_t)kz * pstr;
    if (Ch) { Ch += (size_t)z * zsC; Cl += (size_t)z * zsC; }

    const int tid  = threadIdx.x;
    const int lane = tid & 31;
    const int wid  = tid >> 5;
    const int wm   = wid & 1;
    const int wn   = wid >> 1;
    const int m0 = blockIdx.y * 64;
    const int n0 = blockIdx.x * 64;

    const f16* gsrc[8];
    uint32_t sdst[8];
#pragma unroll
    for (int it = 0; it < 8; ++it) {
        int c = tid + it * 128;
        int a = c >> 8;
        int idx = c & 255;
        int row = idx >> 2;
        int q   = idx & 3;
        const f16* p;
        if (a == 0)      p = Ah + (size_t)(m0 + row) * K;
        else if (a == 1) p = Al + (size_t)(m0 + row) * K;
        else if (a == 2) p = Wh + (size_t)(n0 + row) * K;
        else             p = Wl + (size_t)(n0 + row) * K;
        gsrc[it] = p + kbase + q * 8;
        sdst[it] = a * TILE64 + swz(row * 64 + q * 16);
    }

    const int nch = Klocal >> 5;
    auto issue = [&](int s) {
        uint32_t st = base + (s % 3) * STAGE_BYTES;
#pragma unroll
        for (int it = 0; it < 8; ++it)
            cp16(st + sdst[it], gsrc[it] + s * 32);
    };
    issue(0); CP_COMMIT;
    issue(1); CP_COMMIT;

    const int aRow = wm * 32 + (lane & 15);
    const int aCol = (lane >> 4) * 8;
    const int bRow = wn * 32 + (lane & 7) + ((lane >> 4) << 3);
    const int bCol = ((lane >> 3) & 1) * 8;
    uint32_t a0[2], a1[2], bo[2][2];
#pragma unroll
    for (int kk = 0; kk < 2; ++kk) {
        a0[kk] = swz(aRow * 64 + aCol * 2 + kk * 32);
        a1[kk] = swz((aRow + 16) * 64 + aCol * 2 + kk * 32);
#pragma unroll
        for (int ng = 0; ng < 2; ++ng)
            bo[ng][kk] = swz((bRow + ng * 16) * 64 + bCol * 2 + kk * 32);
    }

    float acc[2][4][4] = {};

    for (int s = 0; s < nch; ++s) {
        CP_WAIT1;
        __syncthreads();
        if (s + 2 < nch) issue(s + 2);
        CP_COMMIT;
        uint32_t st = base + (s % 3) * STAGE_BYTES;
        tile_mma44(st + G_AH, st + G_AL, st + G_BH, st + G_BL,
                   a0, a1, bo, acc);
    }

    const int addb = (kz == 0);
#pragma unroll
    for (int mt = 0; mt < 2; ++mt) {
        int r0 = m0 + wm * 32 + mt * 16 + (lane >> 2);
#pragma unroll
        for (int nt = 0; nt < 4; ++nt) {
            int col = n0 + wn * 32 + nt * 8 + (lane & 3) * 2;
            float b0 = addb ? bias[col] : 0.f, b1 = addb ? bias[col + 1] : 0.f;
            float v0 = acc[mt][nt][0] + b0, v1 = acc[mt][nt][1] + b1;
            float v2 = acc[mt][nt][2] + b0, v3 = acc[mt][nt][3] + b1;
            if (relu) {
                v0 = fmaxf(v0, 0.f); v1 = fmaxf(v1, 0.f);
                v2 = fmaxf(v2, 0.f); v3 = fmaxf(v3, 0.f);
            }
            if (Ch) {
                uint32_t hh, ll;
                split2(v0, v1, hh, ll);
                *(uint32_t*)&Ch[(size_t)r0 * N + col] = hh;
                *(uint32_t*)&Cl[(size_t)r0 * N + col] = ll;
                split2(v2, v3, hh, ll);
                *(uint32_t*)&Ch[(size_t)(r0 + 8) * N + col] = hh;
                *(uint32_t*)&Cl[(size_t)(r0 + 8) * N + col] = ll;
            } else {
                *(float2*)&Cf[(size_t)r0 * N + col]       = make_float2(v0, v1);
                *(float2*)&Cf[(size_t)(r0 + 8) * N + col] = make_float2(v2, v3);
            }
        }
    }
}

// ---------------------------------------------------------------------------
// Relation tensor (single-term fp16): out[b,i,:,:] = ((sub_b * W_bi) @ obj_b^T)
// W_bi = vsub[b,i,:] * vobj[b,i,:] computed in the ws prologue (fused Wv).
// ---------------------------------------------------------------------------
#define RA_STAGE TILE_B     // Ah only
#define RB_STAGE TILE_B     // Bh only
#define REL_SMEM (2048 + 2 * RA_STAGE + 3 * RB_STAGE + 128)  // 43136

__global__ void __launch_bounds__(256, 2) final_tc_kernel(
    const float* __restrict__ sub, const f16* __restrict__ objh,
    const float* __restrict__ vsub, const float* __restrict__ vobj,
    float* __restrict__ out)
{
    extern __shared__ char smch[];
    const uint32_t sb = (smem_u32(smch) + 127) & ~127u;
    float* ws = (float*)(smch + (sb - smem_u32(smch)));
    char* aPtr = (char*)ws + 2048;
    const uint32_t aBase = sb + 2048;
    const uint32_t bBase = aBase + 2 * RA_STAGE;

    const int i = blockIdx.x;
    const int b = blockIdx.y;
    const int tid  = threadIdx.x;
    const int lane = tid & 31;
    const int wid  = tid >> 5;
    const int wm   = wid & 3;
    const int wn   = wid >> 2;

    // W row = vsub * vobj (fused)
    {
        const size_t rb = (size_t)(b * SS + i) * DD;
        float2 a0v = *(const float2*)&vsub[rb + 2 * tid];
        float2 b0v = *(const float2*)&vobj[rb + 2 * tid];
        ws[2 * tid]     = a0v.x * b0v.x;
        ws[2 * tid + 1] = a0v.y * b0v.y;
    }

    const float* subB = sub + (size_t)b * SS * DD;
    const f16* ohB = objh + (size_t)b * SS * DD;

    const f16* bsrc[2];
    uint32_t bdst[2];
#pragma unroll
    for (int it = 0; it < 2; ++it) {
        int c = tid + it * 256;
        int row = c >> 2, q = c & 3;
        bsrc[it] = ohB + (size_t)row * DD + q * 8;
        bdst[it] = swz(row * 64 + q * 16);
    }
    int aLrow[4], aLc4[4];
#pragma unroll
    for (int it = 0; it < 4; ++it) {
        int idx = tid + it * 256;
        aLrow[it] = idx >> 3;
        aLc4[it]  = (idx & 7) << 2;
    }

    auto issueB = [&](int s) {
        uint32_t st = bBase + (s % 3) * RB_STAGE;
#pragma unroll
        for (int it = 0; it < 2; ++it)
            cp16(st + bdst[it], bsrc[it] + s * 32);
    };
    auto loadA = [&](int s, float4* r) {
#pragma unroll
        for (int it = 0; it < 4; ++it)
            r[it] = *(const float4*)&subB[(size_t)aLrow[it] * DD + s * 32 + aLc4[it]];
    };
    auto storeA = [&](int s, const float4* r) {
        char* dh = aPtr + (s & 1) * RA_STAGE;
        int kc = s * 32;
#pragma unroll
        for (int it = 0; it < 4; ++it) {
            float4 v = r[it];
            v.x *= ws[kc + aLc4[it]];     v.y *= ws[kc + aLc4[it] + 1];
            v.z *= ws[kc + aLc4[it] + 2]; v.w *= ws[kc + aLc4[it] + 3];
            uint32_t h0 = pack2(v.x, v.y);
            uint32_t h1 = pack2(v.z, v.w);
            uint32_t off = swz(aLrow[it] * 64 + aLc4[it] * 2);
            *(uint2*)(dh + off) = make_uint2(h0, h1);
        }
    };

    issueB(0); CP_COMMIT;
    issueB(1); CP_COMMIT;
    issueB(2); CP_COMMIT;
    __syncthreads();              // ws visible
    {
        float4 r0[4];
        loadA(0, r0);
        storeA(0, r0);
    }

    const int aRow = wm * 32 + (lane & 15);
    const int aCol = (lane >> 4) * 8;
    const int bRow = wn * 64 + (lane & 7) + ((lane >> 4) << 3);
    const int bCol = ((lane >> 3) & 1) * 8;
    uint32_t a0[2], a1[2], bo[4][2];
#pragma unroll
    for (int kk = 0; kk < 2; ++kk) {
        a0[kk] = swz(aRow * 64 + aCol * 2 + kk * 32);
        a1[kk] = swz((aRow + 16) * 64 + aCol * 2 + kk * 32);
#pragma unroll
        for (int ng = 0; ng < 4; ++ng)
            bo[ng][kk] = swz((bRow + ng * 16) * 64 + bCol * 2 + kk * 32);
    }

    float acc[2][8][4] = {};
    float4 pre[4];

    for (int s = 0; s < 16; ++s) {
        if (s + 1 < 16) loadA(s + 1, pre);
        CP_WAIT2;
        __syncthreads();
        uint32_t aB = aBase + (s & 1) * RA_STAGE;
        uint32_t bB = bBase + (s % 3) * RB_STAGE;
        tile_mma_rel(aB, bB, a0, a1, bo, acc);
        __syncthreads();
        if (s + 1 < 16) storeA(s + 1, pre);
        if (s + 3 < 16) issueB(s + 3);
        CP_COMMIT;
    }

    float* outB = out + (size_t)(b * SS + i) * SS * SS;
#pragma unroll
    for (int mt = 0; mt < 2; ++mt) {
        int r0 = wm * 32 + mt * 16 + (lane >> 2);
#pragma unroll
        for (int nt = 0; nt < 8; ++nt) {
            int col = wn * 64 + nt * 8 + (lane & 3) * 2;
            *(float2*)&outB[(size_t)r0 * SS + col] =
                make_float2(acc[mt][nt][0], acc[mt][nt][1]);
            *(float2*)&outB[(size_t)(r0 + 8) * SS + col] =
                make_float2(acc[mt][nt][2], acc[mt][nt][3]);
        }
    }
}

// ---------------------------------------------------------------------------
// Attention over axis L; 128-thread blocks = 2 (s,h) pairs; fp16 hi/lo out.
// grid (SS, HH/2); group g = tid>>6 selects h = blockIdx.y*2 + g.
// ---------------------------------------------------------------------------
__global__ void attn_kernel(const float* __restrict__ qkv,
                            f16* __restrict__ oh, f16* __restrict__ ol)
{
    const int s = blockIdx.x;
    const int g = threadIdx.x >> 6;
    const int h = blockIdx.y * 2 + g;
    const int t = threadIdx.x & 63;

    __shared__ float qs[2][8][65], ks[2][8][65], vs[2][8][65];
    __shared__ float at[2][8][9];

#pragma unroll
    for (int l = 0; l < 8; ++l) {
        size_t base = (size_t)(l * SS + s) * (3 * DD) + h * HDD + t;
        qs[g][l][t] = qkv[base];
        ks[g][l][t] = qkv[base + DD];
        vs[g][l][t] = qkv[base + 2 * DD];
    }
    __syncthreads();

    const int l = t >> 3;
    const int m = t & 7;
    float sc = 0.0f;
#pragma unroll
    for (int d = 0; d < HDD; ++d) sc += qs[g][l][d] * ks[g][m][d];
    sc *= 0.125f;

    float mx = sc;
#pragma unroll
    for (int off = 1; off < 8; off <<= 1)
        mx = fmaxf(mx, __shfl_xor_sync(0xffffffffu, mx, off));
    float e = __expf(sc - mx);
    float sm = e;
#pragma unroll
    for (int off = 1; off < 8; off <<= 1)
        sm += __shfl_xor_sync(0xffffffffu, sm, off);
    at[g][l][m] = e / sm;
    __syncthreads();

    const int dg = (t & 7) * 8;
    float accv[8] = {};
#pragma unroll
    for (int mm = 0; mm < 8; ++mm) {
        float a = at[g][l][mm];
#pragma unroll
        for (int j = 0; j < 8; ++j)
            accv[j] = fmaf(a, vs[g][mm][dg + j], accv[j]);
    }
    size_t ob = (size_t)(l * SS + s) * DD + h * HDD + dg;
#pragma unroll
    for (int j = 0; j < 8; j += 2) {
        uint32_t hh, ll;
        split2(accv[j], accv[j + 1], hh, ll);
        *(uint32_t*)&oh[ob + j] = hh;
        *(uint32_t*)&ol[ob + j] = ll;
    }
}

// ---------------------------------------------------------------------------
// out = LN(a + sum partials); optional SECOND LN (gam2/bet2) fused on top;
// fp32 store skipped when out==nullptr; fp16 hi/lo emitted when outh.
// ---------------------------------------------------------------------------
__global__ void add_ln_kernel(const float* __restrict__ a,
                              const float* __restrict__ P, int np, int pstr,
                              const float* __restrict__ gam, const float* __restrict__ bet,
                              const float* __restrict__ gam2, const float* __restrict__ bet2,
                              float* __restrict__ out,
                              f16* __restrict__ outh, f16* __restrict__ outl)
{
    const int row = blockIdx.x;
    const int t = threadIdx.x;
    const size_t base = (size_t)row * DD;
    const int c = 2 * t;

    float v0 = a[base + c];
    float v1 = a[base + c + 1];
    for (int p = 0; p < np; ++p) {
        v0 += P[(size_t)p * pstr + base + c];
        v1 += P[(size_t)p * pstr + base + c + 1];
    }

    __shared__ float sred[16];
    auto block_stats = [&](float vv0, float vv1, float& mean, float& rstd) {
        float s = vv0 + vv1;
        float q = vv0 * vv0 + vv1 * vv1;
#pragma unroll
        for (int off = 16; off > 0; off >>= 1) {
            s += __shfl_xor_sync(0xffffffffu, s, off);
            q += __shfl_xor_sync(0xffffffffu, q, off);
        }
        if ((t & 31) == 0) { sred[t >> 5] = s; sred[(t >> 5) + 8] = q; }
        __syncthreads();
        if (t < 32) {
            float ss = (t < 8) ? sred[t] : 0.0f;
            float qq = (t < 8) ? sred[t + 8] : 0.0f;
#pragma unroll
            for (int off = 4; off > 0; off >>= 1) {
                ss += __shfl_xor_sync(0xffffffffu, ss, off);
                qq += __shfl_xor_sync(0xffffffffu, qq, off);
            }
            if (t == 0) { sred[0] = ss; sred[1] = qq; }
        }
        __syncthreads();
        mean = sred[0] * (1.0f / 512.0f);
        float var = sred[1] * (1.0f / 512.0f) - mean * mean;
        rstd = rsqrtf(var + 1e-5f);
    };

    float mean, rstd;
    block_stats(v0, v1, mean, rstd);

    float y0 = (v0 - mean) * rstd * gam[c]     + bet[c];
    float y1 = (v1 - mean) * rstd * gam[c + 1] + bet[c + 1];

    if (gam2) {
        __syncthreads();           // everyone has read sred[0..1]
        float m2, r2;
        block_stats(y0, y1, m2, r2);
        y0 = (y0 - m2) * r2 * gam2[c]     + bet2[c];
        y1 = (y1 - m2) * r2 * gam2[c + 1] + bet2[c + 1];
    }

    if (out) *(float2*)&out[base + c] = make_float2(y0, y1);
    if (outh) {
        uint32_t hh, ll;
        split2(y0, y1, hh, ll);
        *(uint32_t*)&outh[base + c] = hh;
        *(uint32_t*)&outl[base + c] = ll;
    }
}

// ---------------------------------------------------------------------------
// Fused splitter: 8 segments of fp32 -> fp16 hi/lo (one launch).
// ---------------------------------------------------------------------------
struct SplitArgs {
    const float* src[8];
    f16* dh[8];
    f16* dl[8];
    int bstart[9];
};

__global__ void fused_split_kernel(SplitArgs sa)
{
    int blk = blockIdx.x;
    int seg = 0;
#pragma unroll
    for (int s = 1; s < 8; ++s) seg += (blk >= sa.bstart[s]);
    int idx = (blk - sa.bstart[seg]) * 256 + threadIdx.x;
    float4 x = ((const float4*)sa.src[seg])[idx];
    uint32_t h0, h1, l0, l1;
    split2(x.x, x.y, h0, l0);
    split2(x.z, x.w, h1, l1);
    ((uint2*)sa.dh[seg])[idx] = make_uint2(h0, h1);
    ((uint2*)sa.dl[seg])[idx] = make_uint2(l0, l1);
}

// ---------------------------------------------------------------------------
// obj (= P1 slab) -> fp16 (hi only).
// ---------------------------------------------------------------------------
__global__ void obj_split_kernel(const float* __restrict__ P,
                                 f16* __restrict__ oh)
{
    int i = blockIdx.x * blockDim.x + threadIdx.x;   // float4 index
    float4 o = ((const float4*)P)[i + PSTR / 4];
    ((uint2*)oh)[i] = make_uint2(pack2(o.x, o.y), pack2(o.z, o.w));
}

// ---------------------------------------------------------------------------
extern "C" void kernel_launch(void* const* d_in, const int* in_sizes, int n_in,
                              void* d_out, int out_size)
{
    const float* x   = (const float*)d_in[0];
    const float* aiw = (const float*)d_in[1];
    const float* aib = (const float*)d_in[2];
    const float* aow = (const float*)d_in[3];
    const float* aob = (const float*)d_in[4];
    const float* l1w = (const float*)d_in[5];
    const float* l1b = (const float*)d_in[6];
    const float* l2w = (const float*)d_in[7];
    const float* l2b = (const float*)d_in[8];
    const float* f1w = (const float*)d_in[9];
    const float* f1b = (const float*)d_in[10];
    const float* f2w = (const float*)d_in[11];
    const float* f2b = (const float*)d_in[12];
    const float* flw = (const float*)d_in[13];
    const float* flb = (const float*)d_in[14];
    const float* w0  = (const float*)d_in[15];
    const float* b0  = (const float*)d_in[16];
    const float* w1  = (const float*)d_in[17];
    const float* b1  = (const float*)d_in[18];
    const float* w2  = (const float*)d_in[19];
    const float* b2  = (const float*)d_in[20];
    float* out = (float*)d_out;

    f16 *wh, *wl, *s0h, *s0l, *s1h, *s1l;
    float *h, *qkv, *part;
    cudaGetSymbolAddress((void**)&wh,   g_wh);
    cudaGetSymbolAddress((void**)&wl,   g_wl);
    cudaGetSymbolAddress((void**)&s0h,  g_s0h);
    cudaGetSymbolAddress((void**)&s0l,  g_s0l);
    cudaGetSymbolAddress((void**)&s1h,  g_s1h);
    cudaGetSymbolAddress((void**)&s1l,  g_s1l);
    cudaGetSymbolAddress((void**)&h,    g_h);
    cudaGetSymbolAddress((void**)&qkv,  g_qkv);
    cudaGetSymbolAddress((void**)&part, g_part);

    cudaFuncSetAttribute(gemm_f16_kernel,
                         cudaFuncAttributeMaxDynamicSharedMemorySize, GEMM_SMEM);
    cudaFuncSetAttribute(final_tc_kernel,
                         cudaFuncAttributeMaxDynamicSharedMemorySize, REL_SMEM);

    // ---- launch 1: all splits fused (weights + x) ----
    {
        SplitArgs sa;
        sa.src[0] = aiw; sa.dh[0] = wh + OFF_AIW; sa.dl[0] = wl + OFF_AIW;
        sa.src[1] = aow; sa.dh[1] = wh + OFF_AOW; sa.dl[1] = wl + OFF_AOW;
        sa.src[2] = f1w; sa.dh[2] = wh + OFF_F1W; sa.dl[2] = wl + OFF_F1W;
        sa.src[3] = f2w; sa.dh[3] = wh + OFF_F2W; sa.dl[3] = wl + OFF_F2W;
        sa.src[4] = w0;  sa.dh[4] = wh + OFF_W0;  sa.dl[4] = wl + OFF_W0;
        sa.src[5] = w1;  sa.dh[5] = wh + OFF_W1;  sa.dl[5] = wl + OFF_W1;
        sa.src[6] = w2;  sa.dh[6] = wh + OFF_W2;  sa.dl[6] = wl + OFF_W2;
        sa.src[7] = x;   sa.dh[7] = s0h;          sa.dl[7] = s0l;
        int sizes[8] = {2359296, 786432, 3145728, 3145728,
                        1048576, 1048576, 1048576, 524288};
        int acc = 0;
        for (int s = 0; s < 8; ++s) { sa.bstart[s] = acc; acc += sizes[s] / 1024; }
        sa.bstart[8] = acc;
        fused_split_kernel<<<acc, 256>>>(sa);
    }

    // ---- encoder: 3 post-norm layers ----
    for (int i = 0; i < 3; ++i) {
        // qkv: grid (24,16,1)=384 CTAs, 16 chunks each
        gemm_f16_kernel<<<dim3(24, 16, 1), 128, GEMM_SMEM>>>(
            s0h, s0l, wh + OFF_AIW + (size_t)i * 786432, wl + OFF_AIW + (size_t)i * 786432,
            aib + i * 1536, qkv, nullptr, nullptr, 1536, 512, 0, 1, 0, 0, 0, 0, 0);

        attn_kernel<<<dim3(SS, HH / 2), 128>>>(qkv, s1h, s1l);

        // attn-out, split-K4: grid (8,16,4)=512
        gemm_f16_kernel<<<dim3(8, 16, 4), 128, GEMM_SMEM>>>(
            s1h, s1l, wh + OFF_AOW + (size_t)i * 262144, wl + OFF_AOW + (size_t)i * 262144,
            aob + i * 512, part, nullptr, nullptr, 512, 512, 0, 4, PSTR, 0, 0, 0, 0);

        add_ln_kernel<<<NT, 256>>>((i == 0) ? x : h, part, 4, PSTR,
                                   l1w + i * 512, l1b + i * 512,
                                   nullptr, nullptr, h, s0h, s0l);

        // ff1 = relu(...) -> fp16 splits : grid (32,16)=512
        gemm_f16_kernel<<<dim3(32, 16, 1), 128, GEMM_SMEM>>>(
            s0h, s0l, wh + OFF_F1W + (size_t)i * 1048576, wl + OFF_F1W + (size_t)i * 1048576,
            f1b + i * 2048, nullptr, s1h, s1l, 2048, 512, 1, 1, 0, 0, 0, 0, 0);

        // ff2, split-K4 : grid (8,16,4)=512, 16 chunks
        gemm_f16_kernel<<<dim3(8, 16, 4), 128, GEMM_SMEM>>>(
            s1h, s1l, wh + OFF_F2W + (size_t)i * 1048576, wl + OFF_F2W + (size_t)i * 1048576,
            f2b + i * 512, part, nullptr, nullptr, 512, 2048, 0, 4, PSTR, 0, 0, 0, 0);

        if (i < 2) {
            add_ln_kernel<<<NT, 256>>>(h, part, 4, PSTR,
                                       l2w + i * 512, l2b + i * 512,
                                       nullptr, nullptr, h, s0h, s0l);
        } else {
            // layer-2 LN2 fused with final encoder LN; fp32 store dead -> skipped
            add_ln_kernel<<<NT, 256>>>(h, part, 4, PSTR,
                                       l2w + i * 512, l2b + i * 512,
                                       flw, flb, nullptr, s0h, s0l);
        }
    }

    // ---- 4 projection MLPs, batched via blockIdx.z ----
    const int ZW = 262144, ZB = 512, ZC = NT * DD;
    gemm_f16_kernel<<<dim3(8, 16, 4), 128, GEMM_SMEM>>>(
        s0h, s0l, wh + OFF_W0, wl + OFF_W0, b0, nullptr, s1h, s1l,
        512, 512, 1, 1, 0, 0, ZW, ZB, ZC);
    gemm_f16_kernel<<<dim3(8, 16, 4), 128, GEMM_SMEM>>>(
        s1h, s1l, wh + OFF_W1, wl + OFF_W1, b1, nullptr, s0h, s0l,
        512, 512, 1, 1, 0, ZC, ZW, ZB, ZC);
    // mlp2: 4 z-batched fp32 outputs -> part slabs [sub|obj|vsub|vobj]
    gemm_f16_kernel<<<dim3(8, 16, 4), 128, GEMM_SMEM>>>(
        s0h, s0l, wh + OFF_W2, wl + OFF_W2, b2, part, nullptr, nullptr,
        512, 512, 0, 1, 0, ZC, ZW, ZB, PSTR);

    // obj -> fp16 (hi)
    obj_split_kernel<<<512, 256>>>(part, s1h);

    // relation tensor: (8, 128, 128, 128), single-term fp16, fused Wv
    final_tc_kernel<<<dim3(SS, LL), 256, REL_SMEM>>>(
        part, s1h, part + (size_t)2 * PSTR, part + (size_t)3 * PSTR, out);
}

// round 17
// speedup vs baseline: 1.0227x; 1.0006x over previous
#include <cuda_runtime.h>
#include <cuda_fp16.h>
#include <math.h>
#include <stdint.h>

// ---------------------------------------------------------------------------
// GraphDecoder on tensor cores (mma.sync fp16, hi/lo split, fp32 acc).
// Round 17 = R16 (best, 397.2us) + attn-out split-K 4 -> 2:
//  - grid 256 = one clean wave at 2 CTAs/SM; add_ln partial traffic halved
// All other structure frozen at measured-best:
//  - encoder/MLP GEMMs fp16 3-term (64x64 tiles, 128thr, 3-stage, 4 CTA/SM)
//  - relation kernel single-term fp16 + fused Wv
//  - fused final LN, dead-store skip, 128-thread attn
// ---------------------------------------------------------------------------

#define LL  8
#define SS  128
#define DD  512
#define HH  8
#define HDD 64
#define NT  1024

typedef __half f16;

// ---- persistent scratch ----------------------------------------------------
#define OFF_AIW 0            // 3 x 786432
#define OFF_AOW 2359296      // 3 x 262144
#define OFF_F1W 3145728      // 3 x 1048576
#define OFF_F2W 6291456      // 3 x 1048576
#define OFF_W0  9437184      // 4 x 262144
#define OFF_W1  10485760
#define OFF_W2  11534336
#define WTOT    12582912

#define PSTR  (NT * DD)           // 524288 floats per partial slab

__device__ f16   g_wh[WTOT], g_wl[WTOT];
__device__ f16   g_s0h[4 * NT * DD], g_s0l[4 * NT * DD];
__device__ f16   g_s1h[4 * NT * DD], g_s1l[4 * NT * DD];
__device__ float g_h[NT * DD];
__device__ float g_qkv[NT * 3 * DD];
__device__ float g_part[8 * NT * DD];      // split-K / batch partial arena

// ========================= low-level helpers ================================
__device__ __forceinline__ uint32_t smem_u32(const void* p) {
    uint32_t a;
    asm("{ .reg .u64 t; cvta.to.shared.u64 t, %1; cvt.u32.u64 %0, t; }"
        : "=r"(a) : "l"(p));
    return a;
}

// swizzle for 64-byte rows: XOR bits [4:6) with bits [7:9)
__device__ __forceinline__ uint32_t swz(uint32_t off) {
    return off ^ (((off >> 7) & 3u) << 4);
}

__device__ __forceinline__ void ldmx4(uint32_t* r, uint32_t addr) {
    asm volatile("ldmatrix.sync.aligned.m8n8.x4.shared.b16 {%0,%1,%2,%3}, [%4];"
        : "=r"(r[0]), "=r"(r[1]), "=r"(r[2]), "=r"(r[3]) : "r"(addr));
}

__device__ __forceinline__ void mma16816(float* d, const uint32_t* a,
                                         const uint32_t* b) {
    asm volatile(
        "mma.sync.aligned.m16n8k16.row.col.f32.f16.f16.f32 "
        "{%0,%1,%2,%3}, {%4,%5,%6,%7}, {%8,%9}, {%0,%1,%2,%3};"
        : "+f"(d[0]), "+f"(d[1]), "+f"(d[2]), "+f"(d[3])
        : "r"(a[0]), "r"(a[1]), "r"(a[2]), "r"(a[3]), "r"(b[0]), "r"(b[1]));
}

__device__ __forceinline__ void cp16(uint32_t smem, const void* g) {
    asm volatile("cp.async.cg.shared.global [%0], [%1], 16;"
        :: "r"(smem), "l"(g));
}
#define CP_COMMIT asm volatile("cp.async.commit_group;" ::: "memory")
#define CP_WAIT1  asm volatile("cp.async.wait_group 1;" ::: "memory")
#define CP_WAIT2  asm volatile("cp.async.wait_group 2;" ::: "memory")

__device__ __forceinline__ void split2(float x, float y, uint32_t& hi, uint32_t& lo) {
    __half2 h, l;
    h.x = __float2half(x); h.y = __float2half(y);
    l.x = __float2half(x - __half2float(h.x));
    l.y = __float2half(y - __half2float(h.y));
    hi = *(uint32_t*)&h; lo = *(uint32_t*)&l;
}

__device__ __forceinline__ uint32_t pack2(float x, float y) {
    __half2 h;
    h.x = __float2half(x); h.y = __float2half(y);
    return *(uint32_t*)&h;
}

#define TILE_B  8192   // 128x32 f16 tile
#define TILE64  4096   // 64x32 f16 tile

// ---------------------------------------------------------------------------
// GEMM tile-mma (64x64, 4 warps 2m x 2n): A both-kk prefetch, term-outermost.
// ---------------------------------------------------------------------------
__device__ __forceinline__ void tile_mma44(
    uint32_t ahB, uint32_t alB, uint32_t bhB, uint32_t blB,
    const uint32_t* a0, const uint32_t* a1, const uint32_t (*bo)[2],
    float (&acc)[2][4][4])
{
    uint32_t ah[2][2][4], al[2][2][4];   // [kk][mt][4]
#pragma unroll
    for (int kk = 0; kk < 2; ++kk) {
        ldmx4(ah[kk][0], ahB + a0[kk]);
        ldmx4(ah[kk][1], ahB + a1[kk]);
        ldmx4(al[kk][0], alB + a0[kk]);
        ldmx4(al[kk][1], alB + a1[kk]);
    }
#pragma unroll
    for (int kk = 0; kk < 2; ++kk) {
        uint32_t bh[4][2], bl[4][2];
#pragma unroll
        for (int ng = 0; ng < 2; ++ng) {
            uint32_t r[4];
            ldmx4(r, bhB + bo[ng][kk]);
            bh[2*ng][0] = r[0]; bh[2*ng][1] = r[1];
            bh[2*ng+1][0] = r[2]; bh[2*ng+1][1] = r[3];
            ldmx4(r, blB + bo[ng][kk]);
            bl[2*ng][0] = r[0]; bl[2*ng][1] = r[1];
            bl[2*ng+1][0] = r[2]; bl[2*ng+1][1] = r[3];
        }
#pragma unroll
        for (int mt = 0; mt < 2; ++mt)
#pragma unroll
            for (int nt = 0; nt < 4; ++nt)
                mma16816(acc[mt][nt], ah[kk][mt], bh[nt]);
#pragma unroll
        for (int mt = 0; mt < 2; ++mt)
#pragma unroll
            for (int nt = 0; nt < 4; ++nt)
                mma16816(acc[mt][nt], ah[kk][mt], bl[nt]);
#pragma unroll
        for (int mt = 0; mt < 2; ++mt)
#pragma unroll
            for (int nt = 0; nt < 4; ++nt)
                mma16816(acc[mt][nt], al[kk][mt], bh[nt]);
    }
}

// ---------------------------------------------------------------------------
// Relation tile-mma (128x128, SINGLE term): acc[2][8][4].
// ---------------------------------------------------------------------------
__device__ __forceinline__ void tile_mma_rel(
    uint32_t ahB, uint32_t bhB,
    const uint32_t* a0, const uint32_t* a1, const uint32_t (*bo)[2],
    float (&acc)[2][8][4])
{
#pragma unroll
    for (int kk = 0; kk < 2; ++kk) {
        uint32_t ah[2][4];
        ldmx4(ah[0], ahB + a0[kk]);
        ldmx4(ah[1], ahB + a1[kk]);
#pragma unroll
        for (int hf = 0; hf < 2; ++hf) {
            uint32_t bh[4][2];
#pragma unroll
            for (int ng = 0; ng < 2; ++ng) {
                uint32_t r[4];
                ldmx4(r, bhB + bo[2 * hf + ng][kk]);
                bh[2*ng][0] = r[0]; bh[2*ng][1] = r[1];
                bh[2*ng+1][0] = r[2]; bh[2*ng+1][1] = r[3];
            }
#pragma unroll
            for (int mt = 0; mt < 2; ++mt)
#pragma unroll
                for (int nt = 0; nt < 4; ++nt)
                    mma16816(acc[mt][4*hf + nt], ah[mt], bh[nt]);
        }
    }
}

// ---------------------------------------------------------------------------
// f16 GEMM (3-term), batched (z) + split-K (ks).
// 64x64 tile, 128 threads, BK=32, 3-stage ring, ONE sync/chunk, 4 CTAs/SM.
// ---------------------------------------------------------------------------
#define G_AH 0
#define G_AL 4096
#define G_BH 8192
#define G_BL 12288
#define STAGE_BYTES 16384
#define GEMM_SMEM   (3 * STAGE_BYTES + 128)   // 49280

__global__ void __launch_bounds__(128, 4) gemm_f16_kernel(
    const f16* __restrict__ Ah, const f16* __restrict__ Al,
    const f16* __restrict__ Wh, const f16* __restrict__ Wl,
    const float* __restrict__ bias,
    float* __restrict__ Cf, f16* __restrict__ Ch, f16* __restrict__ Cl,
    int N, int K, int relu, int ks, int pstr,
    int zsA, int zsW, int zsB, int zsC)
{
    extern __shared__ char smch[];
    const uint32_t base = (smem_u32(smch) + 127) & ~127u;

    const int z  = blockIdx.z / ks;
    const int kz = blockIdx.z % ks;
    const int Klocal = K / ks;
    const int kbase = kz * Klocal;

    Ah += (size_t)z * zsA;  Al += (size_t)z * zsA;
    Wh += (size_t)z * zsW;  Wl += (size_t)z * zsW;
    bias += (size_t)z * zsB;
    if (Cf) Cf += (size_t)z * zsC + (size_t)kz * pstr;
    if (Ch) { Ch += (size_t)z * zsC; Cl += (size_t)z * zsC; }

    const int tid  = threadIdx.x;
    const int lane = tid & 31;
    const int wid  = tid >> 5;
    const int wm   = wid & 1;
    const int wn   = wid >> 1;
    const int m0 = blockIdx.y * 64;
    const int n0 = blockIdx.x * 64;

    const f16* gsrc[8];
    uint32_t sdst[8];
#pragma unroll
    for (int it = 0; it < 8; ++it) {
        int c = tid + it * 128;
        int a = c >> 8;
        int idx = c & 255;
        int row = idx >> 2;
        int q   = idx & 3;
        const f16* p;
        if (a == 0)      p = Ah + (size_t)(m0 + row) * K;
        else if (a == 1) p = Al + (size_t)(m0 + row) * K;
        else if (a == 2) p = Wh + (size_t)(n0 + row) * K;
        else             p = Wl + (size_t)(n0 + row) * K;
        gsrc[it] = p + kbase + q * 8;
        sdst[it] = a * TILE64 + swz(row * 64 + q * 16);
    }

    const int nch = Klocal >> 5;
    auto issue = [&](int s) {
        uint32_t st = base + (s % 3) * STAGE_BYTES;
#pragma unroll
        for (int it = 0; it < 8; ++it)
            cp16(st + sdst[it], gsrc[it] + s * 32);
    };
    issue(0); CP_COMMIT;
    issue(1); CP_COMMIT;

    const int aRow = wm * 32 + (lane & 15);
    const int aCol = (lane >> 4) * 8;
    const int bRow = wn * 32 + (lane & 7) + ((lane >> 4) << 3);
    const int bCol = ((lane >> 3) & 1) * 8;
    uint32_t a0[2], a1[2], bo[2][2];
#pragma unroll
    for (int kk = 0; kk < 2; ++kk) {
        a0[kk] = swz(aRow * 64 + aCol * 2 + kk * 32);
        a1[kk] = swz((aRow + 16) * 64 + aCol * 2 + kk * 32);
#pragma unroll
        for (int ng = 0; ng < 2; ++ng)
            bo[ng][kk] = swz((bRow + ng * 16) * 64 + bCol * 2 + kk * 32);
    }

    float acc[2][4][4] = {};

    for (int s = 0; s < nch; ++s) {
        CP_WAIT1;
        __syncthreads();
        if (s + 2 < nch) issue(s + 2);
        CP_COMMIT;
        uint32_t st = base + (s % 3) * STAGE_BYTES;
        tile_mma44(st + G_AH, st + G_AL, st + G_BH, st + G_BL,
                   a0, a1, bo, acc);
    }

    const int addb = (kz == 0);
#pragma unroll
    for (int mt = 0; mt < 2; ++mt) {
        int r0 = m0 + wm * 32 + mt * 16 + (lane >> 2);
#pragma unroll
        for (int nt = 0; nt < 4; ++nt) {
            int col = n0 + wn * 32 + nt * 8 + (lane & 3) * 2;
            float b0 = addb ? bias[col] : 0.f, b1 = addb ? bias[col + 1] : 0.f;
            float v0 = acc[mt][nt][0] + b0, v1 = acc[mt][nt][1] + b1;
            float v2 = acc[mt][nt][2] + b0, v3 = acc[mt][nt][3] + b1;
            if (relu) {
                v0 = fmaxf(v0, 0.f); v1 = fmaxf(v1, 0.f);
                v2 = fmaxf(v2, 0.f); v3 = fmaxf(v3, 0.f);
            }
            if (Ch) {
                uint32_t hh, ll;
                split2(v0, v1, hh, ll);
                *(uint32_t*)&Ch[(size_t)r0 * N + col] = hh;
                *(uint32_t*)&Cl[(size_t)r0 * N + col] = ll;
                split2(v2, v3, hh, ll);
                *(uint32_t*)&Ch[(size_t)(r0 + 8) * N + col] = hh;
                *(uint32_t*)&Cl[(size_t)(r0 + 8) * N + col] = ll;
            } else {
                *(float2*)&Cf[(size_t)r0 * N + col]       = make_float2(v0, v1);
                *(float2*)&Cf[(size_t)(r0 + 8) * N + col] = make_float2(v2, v3);
            }
        }
    }
}

// ---------------------------------------------------------------------------
// Relation tensor (single-term fp16): out[b,i,:,:] = ((sub_b * W_bi) @ obj_b^T)
// W_bi = vsub[b,i,:] * vobj[b,i,:] computed in the ws prologue (fused Wv).
// ---------------------------------------------------------------------------
#define RA_STAGE TILE_B     // Ah only
#define RB_STAGE TILE_B     // Bh only
#define REL_SMEM (2048 + 2 * RA_STAGE + 3 * RB_STAGE + 128)  // 43136

__global__ void __launch_bounds__(256, 2) final_tc_kernel(
    const float* __restrict__ sub, const f16* __restrict__ objh,
    const float* __restrict__ vsub, const float* __restrict__ vobj,
    float* __restrict__ out)
{
    extern __shared__ char smch[];
    const uint32_t sb = (smem_u32(smch) + 127) & ~127u;
    float* ws = (float*)(smch + (sb - smem_u32(smch)));
    char* aPtr = (char*)ws + 2048;
    const uint32_t aBase = sb + 2048;
    const uint32_t bBase = aBase + 2 * RA_STAGE;

    const int i = blockIdx.x;
    const int b = blockIdx.y;
    const int tid  = threadIdx.x;
    const int lane = tid & 31;
    const int wid  = tid >> 5;
    const int wm   = wid & 3;
    const int wn   = wid >> 2;

    // W row = vsub * vobj (fused)
    {
        const size_t rb = (size_t)(b * SS + i) * DD;
        float2 a0v = *(const float2*)&vsub[rb + 2 * tid];
        float2 b0v = *(const float2*)&vobj[rb + 2 * tid];
        ws[2 * tid]     = a0v.x * b0v.x;
        ws[2 * tid + 1] = a0v.y * b0v.y;
    }

    const float* subB = sub + (size_t)b * SS * DD;
    const f16* ohB = objh + (size_t)b * SS * DD;

    const f16* bsrc[2];
    uint32_t bdst[2];
#pragma unroll
    for (int it = 0; it < 2; ++it) {
        int c = tid + it * 256;
        int row = c >> 2, q = c & 3;
        bsrc[it] = ohB + (size_t)row * DD + q * 8;
        bdst[it] = swz(row * 64 + q * 16);
    }
    int aLrow[4], aLc4[4];
#pragma unroll
    for (int it = 0; it < 4; ++it) {
        int idx = tid + it * 256;
        aLrow[it] = idx >> 3;
        aLc4[it]  = (idx & 7) << 2;
    }

    auto issueB = [&](int s) {
        uint32_t st = bBase + (s % 3) * RB_STAGE;
#pragma unroll
        for (int it = 0; it < 2; ++it)
            cp16(st + bdst[it], bsrc[it] + s * 32);
    };
    auto loadA = [&](int s, float4* r) {
#pragma unroll
        for (int it = 0; it < 4; ++it)
            r[it] = *(const float4*)&subB[(size_t)aLrow[it] * DD + s * 32 + aLc4[it]];
    };
    auto storeA = [&](int s, const float4* r) {
        char* dh = aPtr + (s & 1) * RA_STAGE;
        int kc = s * 32;
#pragma unroll
        for (int it = 0; it < 4; ++it) {
            float4 v = r[it];
            v.x *= ws[kc + aLc4[it]];     v.y *= ws[kc + aLc4[it] + 1];
            v.z *= ws[kc + aLc4[it] + 2]; v.w *= ws[kc + aLc4[it] + 3];
            uint32_t h0 = pack2(v.x, v.y);
            uint32_t h1 = pack2(v.z, v.w);
            uint32_t off = swz(aLrow[it] * 64 + aLc4[it] * 2);
            *(uint2*)(dh + off) = make_uint2(h0, h1);
        }
    };

    issueB(0); CP_COMMIT;
    issueB(1); CP_COMMIT;
    issueB(2); CP_COMMIT;
    __syncthreads();              // ws visible
    {
        float4 r0[4];
        loadA(0, r0);
        storeA(0, r0);
    }

    const int aRow = wm * 32 + (lane & 15);
    const int aCol = (lane >> 4) * 8;
    const int bRow = wn * 64 + (lane & 7) + ((lane >> 4) << 3);
    const int bCol = ((lane >> 3) & 1) * 8;
    uint32_t a0[2], a1[2], bo[4][2];
#pragma unroll
    for (int kk = 0; kk < 2; ++kk) {
        a0[kk] = swz(aRow * 64 + aCol * 2 + kk * 32);
        a1[kk] = swz((aRow + 16) * 64 + aCol * 2 + kk * 32);
#pragma unroll
        for (int ng = 0; ng < 4; ++ng)
            bo[ng][kk] = swz((bRow + ng * 16) * 64 + bCol * 2 + kk * 32);
    }

    float acc[2][8][4] = {};
    float4 pre[4];

    for (int s = 0; s < 16; ++s) {
        if (s + 1 < 16) loadA(s + 1, pre);
        CP_WAIT2;
        __syncthreads();
        uint32_t aB = aBase + (s & 1) * RA_STAGE;
        uint32_t bB = bBase + (s % 3) * RB_STAGE;
        tile_mma_rel(aB, bB, a0, a1, bo, acc);
        __syncthreads();
        if (s + 1 < 16) storeA(s + 1, pre);
        if (s + 3 < 16) issueB(s + 3);
        CP_COMMIT;
    }

    float* outB = out + (size_t)(b * SS + i) * SS * SS;
#pragma unroll
    for (int mt = 0; mt < 2; ++mt) {
        int r0 = wm * 32 + mt * 16 + (lane >> 2);
#pragma unroll
        for (int nt = 0; nt < 8; ++nt) {
            int col = wn * 64 + nt * 8 + (lane & 3) * 2;
            *(float2*)&outB[(size_t)r0 * SS + col] =
                make_float2(acc[mt][nt][0], acc[mt][nt][1]);
            *(float2*)&outB[(size_t)(r0 + 8) * SS + col] =
                make_float2(acc[mt][nt][2], acc[mt][nt][3]);
        }
    }
}

// ---------------------------------------------------------------------------
// Attention over axis L; 128-thread blocks = 2 (s,h) pairs; fp16 hi/lo out.
// ---------------------------------------------------------------------------
__global__ void attn_kernel(const float* __restrict__ qkv,
                            f16* __restrict__ oh, f16* __restrict__ ol)
{
    const int s = blockIdx.x;
    const int g = threadIdx.x >> 6;
    const int h = blockIdx.y * 2 + g;
    const int t = threadIdx.x & 63;

    __shared__ float qs[2][8][65], ks[2][8][65], vs[2][8][65];
    __shared__ float at[2][8][9];

#pragma unroll
    for (int l = 0; l < 8; ++l) {
        size_t base = (size_t)(l * SS + s) * (3 * DD) + h * HDD + t;
        qs[g][l][t] = qkv[base];
        ks[g][l][t] = qkv[base + DD];
        vs[g][l][t] = qkv[base + 2 * DD];
    }
    __syncthreads();

    const int l = t >> 3;
    const int m = t & 7;
    float sc = 0.0f;
#pragma unroll
    for (int d = 0; d < HDD; ++d) sc += qs[g][l][d] * ks[g][m][d];
    sc *= 0.125f;

    float mx = sc;
#pragma unroll
    for (int off = 1; off < 8; off <<= 1)
        mx = fmaxf(mx, __shfl_xor_sync(0xffffffffu, mx, off));
    float e = __expf(sc - mx);
    float sm = e;
#pragma unroll
    for (int off = 1; off < 8; off <<= 1)
        sm += __shfl_xor_sync(0xffffffffu, sm, off);
    at[g][l][m] = e / sm;
    __syncthreads();

    const int dg = (t & 7) * 8;
    float accv[8] = {};
#pragma unroll
    for (int mm = 0; mm < 8; ++mm) {
        float a = at[g][l][mm];
#pragma unroll
        for (int j = 0; j < 8; ++j)
            accv[j] = fmaf(a, vs[g][mm][dg + j], accv[j]);
    }
    size_t ob = (size_t)(l * SS + s) * DD + h * HDD + dg;
#pragma unroll
    for (int j = 0; j < 8; j += 2) {
        uint32_t hh, ll;
        split2(accv[j], accv[j + 1], hh, ll);
        *(uint32_t*)&oh[ob + j] = hh;
        *(uint32_t*)&ol[ob + j] = ll;
    }
}

// ---------------------------------------------------------------------------
// out = LN(a + sum partials); optional SECOND LN fused; fp32 store optional.
// ---------------------------------------------------------------------------
__global__ void add_ln_kernel(const float* __restrict__ a,
                              const float* __restrict__ P, int np, int pstr,
                              const float* __restrict__ gam, const float* __restrict__ bet,
                              const float* __restrict__ gam2, const float* __restrict__ bet2,
                              float* __restrict__ out,
                              f16* __restrict__ outh, f16* __restrict__ outl)
{
    const int row = blockIdx.x;
    const int t = threadIdx.x;
    const size_t base = (size_t)row * DD;
    const int c = 2 * t;

    float v0 = a[base + c];
    float v1 = a[base + c + 1];
    for (int p = 0; p < np; ++p) {
        v0 += P[(size_t)p * pstr + base + c];
        v1 += P[(size_t)p * pstr + base + c + 1];
    }

    __shared__ float sred[16];
    auto block_stats = [&](float vv0, float vv1, float& mean, float& rstd) {
        float s = vv0 + vv1;
        float q = vv0 * vv0 + vv1 * vv1;
#pragma unroll
        for (int off = 16; off > 0; off >>= 1) {
            s += __shfl_xor_sync(0xffffffffu, s, off);
            q += __shfl_xor_sync(0xffffffffu, q, off);
        }
        if ((t & 31) == 0) { sred[t >> 5] = s; sred[(t >> 5) + 8] = q; }
        __syncthreads();
        if (t < 32) {
            float ss = (t < 8) ? sred[t] : 0.0f;
            float qq = (t < 8) ? sred[t + 8] : 0.0f;
#pragma unroll
            for (int off = 4; off > 0; off >>= 1) {
                ss += __shfl_xor_sync(0xffffffffu, ss, off);
                qq += __shfl_xor_sync(0xffffffffu, qq, off);
            }
            if (t == 0) { sred[0] = ss; sred[1] = qq; }
        }
        __syncthreads();
        mean = sred[0] * (1.0f / 512.0f);
        float var = sred[1] * (1.0f / 512.0f) - mean * mean;
        rstd = rsqrtf(var + 1e-5f);
    };

    float mean, rstd;
    block_stats(v0, v1, mean, rstd);

    float y0 = (v0 - mean) * rstd * gam[c]     + bet[c];
    float y1 = (v1 - mean) * rstd * gam[c + 1] + bet[c + 1];

    if (gam2) {
        __syncthreads();
        float m2, r2;
        block_stats(y0, y1, m2, r2);
        y0 = (y0 - m2) * r2 * gam2[c]     + bet2[c];
        y1 = (y1 - m2) * r2 * gam2[c + 1] + bet2[c + 1];
    }

    if (out) *(float2*)&out[base + c] = make_float2(y0, y1);
    if (outh) {
        uint32_t hh, ll;
        split2(y0, y1, hh, ll);
        *(uint32_t*)&outh[base + c] = hh;
        *(uint32_t*)&outl[base + c] = ll;
    }
}

// ---------------------------------------------------------------------------
// Fused splitter: 8 segments of fp32 -> fp16 hi/lo (one launch).
// ---------------------------------------------------------------------------
struct SplitArgs {
    const float* src[8];
    f16* dh[8];
    f16* dl[8];
    int bstart[9];
};

__global__ void fused_split_kernel(SplitArgs sa)
{
    int blk = blockIdx.x;
    int seg = 0;
#pragma unroll
    for (int s = 1; s < 8; ++s) seg += (blk >= sa.bstart[s]);
    int idx = (blk - sa.bstart[seg]) * 256 + threadIdx.x;
    float4 x = ((const float4*)sa.src[seg])[idx];
    uint32_t h0, h1, l0, l1;
    split2(x.x, x.y, h0, l0);
    split2(x.z, x.w, h1, l1);
    ((uint2*)sa.dh[seg])[idx] = make_uint2(h0, h1);
    ((uint2*)sa.dl[seg])[idx] = make_uint2(l0, l1);
}

// ---------------------------------------------------------------------------
// obj (= P1 slab) -> fp16 (hi only).
// ---------------------------------------------------------------------------
__global__ void obj_split_kernel(const float* __restrict__ P,
                                 f16* __restrict__ oh)
{
    int i = blockIdx.x * blockDim.x + threadIdx.x;   // float4 index
    float4 o = ((const float4*)P)[i + PSTR / 4];
    ((uint2*)oh)[i] = make_uint2(pack2(o.x, o.y), pack2(o.z, o.w));
}

// ---------------------------------------------------------------------------
extern "C" void kernel_launch(void* const* d_in, const int* in_sizes, int n_in,
                              void* d_out, int out_size)
{
    const float* x   = (const float*)d_in[0];
    const float* aiw = (const float*)d_in[1];
    const float* aib = (const float*)d_in[2];
    const float* aow = (const float*)d_in[3];
    const float* aob = (const float*)d_in[4];
    const float* l1w = (const float*)d_in[5];
    const float* l1b = (const float*)d_in[6];
    const float* l2w = (const float*)d_in[7];
    const float* l2b = (const float*)d_in[8];
    const float* f1w = (const float*)d_in[9];
    const float* f1b = (const float*)d_in[10];
    const float* f2w = (const float*)d_in[11];
    const float* f2b = (const float*)d_in[12];
    const float* flw = (const float*)d_in[13];
    const float* flb = (const float*)d_in[14];
    const float* w0  = (const float*)d_in[15];
    const float* b0  = (const float*)d_in[16];
    const float* w1  = (const float*)d_in[17];
    const float* b1  = (const float*)d_in[18];
    const float* w2  = (const float*)d_in[19];
    const float* b2  = (const float*)d_in[20];
    float* out = (float*)d_out;

    f16 *wh, *wl, *s0h, *s0l, *s1h, *s1l;
    float *h, *qkv, *part;
    cudaGetSymbolAddress((void**)&wh,   g_wh);
    cudaGetSymbolAddress((void**)&wl,   g_wl);
    cudaGetSymbolAddress((void**)&s0h,  g_s0h);
    cudaGetSymbolAddress((void**)&s0l,  g_s0l);
    cudaGetSymbolAddress((void**)&s1h,  g_s1h);
    cudaGetSymbolAddress((void**)&s1l,  g_s1l);
    cudaGetSymbolAddress((void**)&h,    g_h);
    cudaGetSymbolAddress((void**)&qkv,  g_qkv);
    cudaGetSymbolAddress((void**)&part, g_part);

    cudaFuncSetAttribute(gemm_f16_kernel,
                         cudaFuncAttributeMaxDynamicSharedMemorySize, GEMM_SMEM);
    cudaFuncSetAttribute(final_tc_kernel,
                         cudaFuncAttributeMaxDynamicSharedMemorySize, REL_SMEM);

    // ---- launch 1: all splits fused (weights + x) ----
    {
        SplitArgs sa;
        sa.src[0] = aiw; sa.dh[0] = wh + OFF_AIW; sa.dl[0] = wl + OFF_AIW;
        sa.src[1] = aow; sa.dh[1] = wh + OFF_AOW; sa.dl[1] = wl + OFF_AOW;
        sa.src[2] = f1w; sa.dh[2] = wh + OFF_F1W; sa.dl[2] = wl + OFF_F1W;
        sa.src[3] = f2w; sa.dh[3] = wh + OFF_F2W; sa.dl[3] = wl + OFF_F2W;
        sa.src[4] = w0;  sa.dh[4] = wh + OFF_W0;  sa.dl[4] = wl + OFF_W0;
        sa.src[5] = w1;  sa.dh[5] = wh + OFF_W1;  sa.dl[5] = wl + OFF_W1;
        sa.src[6] = w2;  sa.dh[6] = wh + OFF_W2;  sa.dl[6] = wl + OFF_W2;
        sa.src[7] = x;   sa.dh[7] = s0h;          sa.dl[7] = s0l;
        int sizes[8] = {2359296, 786432, 3145728, 3145728,
                        1048576, 1048576, 1048576, 524288};
        int acc = 0;
        for (int s = 0; s < 8; ++s) { sa.bstart[s] = acc; acc += sizes[s] / 1024; }
        sa.bstart[8] = acc;
        fused_split_kernel<<<acc, 256>>>(sa);
    }

    // ---- encoder: 3 post-norm layers ----
    for (int i = 0; i < 3; ++i) {
        // qkv: grid (24,16,1)=384 CTAs, 16 chunks each
        gemm_f16_kernel<<<dim3(24, 16, 1), 128, GEMM_SMEM>>>(
            s0h, s0l, wh + OFF_AIW + (size_t)i * 786432, wl + OFF_AIW + (size_t)i * 786432,
            aib + i * 1536, qkv, nullptr, nullptr, 1536, 512, 0, 1, 0, 0, 0, 0, 0);

        attn_kernel<<<dim3(SS, HH / 2), 128>>>(qkv, s1h, s1l);

        // attn-out, split-K2: grid (8,16,2)=256 (one clean wave), 8 chunks
        gemm_f16_kernel<<<dim3(8, 16, 2), 128, GEMM_SMEM>>>(
            s1h, s1l, wh + OFF_AOW + (size_t)i * 262144, wl + OFF_AOW + (size_t)i * 262144,
            aob + i * 512, part, nullptr, nullptr, 512, 512, 0, 2, PSTR, 0, 0, 0, 0);

        add_ln_kernel<<<NT, 256>>>((i == 0) ? x : h, part, 2, PSTR,
                                   l1w + i * 512, l1b + i * 512,
                                   nullptr, nullptr, h, s0h, s0l);

        // ff1 = relu(...) -> fp16 splits : grid (32,16)=512
        gemm_f16_kernel<<<dim3(32, 16, 1), 128, GEMM_SMEM>>>(
            s0h, s0l, wh + OFF_F1W + (size_t)i * 1048576, wl + OFF_F1W + (size_t)i * 1048576,
            f1b + i * 2048, nullptr, s1h, s1l, 2048, 512, 1, 1, 0, 0, 0, 0, 0);

        // ff2, split-K4 : grid (8,16,4)=512, 16 chunks
        gemm_f16_kernel<<<dim3(8, 16, 4), 128, GEMM_SMEM>>>(
            s1h, s1l, wh + OFF_F2W + (size_t)i * 1048576, wl + OFF_F2W + (size_t)i * 1048576,
            f2b + i * 512, part, nullptr, nullptr, 512, 2048, 0, 4, PSTR, 0, 0, 0, 0);

        if (i < 2) {
            add_ln_kernel<<<NT, 256>>>(h, part, 4, PSTR,
                                       l2w + i * 512, l2b + i * 512,
                                       nullptr, nullptr, h, s0h, s0l);
        } else {
            // layer-2 LN2 fused with final encoder LN; dead fp32 store skipped
            add_ln_kernel<<<NT, 256>>>(h, part, 4, PSTR,
                                       l2w + i * 512, l2b + i * 512,
                                       flw, flb, nullptr, s0h, s0l);
        }
    }

    // ---- 4 projection MLPs, batched via blockIdx.z ----
    const int ZW = 262144, ZB = 512, ZC = NT * DD;
    gemm_f16_kernel<<<dim3(8, 16, 4), 128, GEMM_SMEM>>>(
        s0h, s0l, wh + OFF_W0, wl + OFF_W0, b0, nullptr, s1h, s1l,
        512, 512, 1, 1, 0, 0, ZW, ZB, ZC);
    gemm_f16_kernel<<<dim3(8, 16, 4), 128, GEMM_SMEM>>>(
        s1h, s1l, wh + OFF_W1, wl + OFF_W1, b1, nullptr, s0h, s0l,
        512, 512, 1, 1, 0, ZC, ZW, ZB, ZC);
    // mlp2: 4 z-batched fp32 outputs -> part slabs [sub|obj|vsub|vobj]
    gemm_f16_kernel<<<dim3(8, 16, 4), 128, GEMM_SMEM>>>(
        s0h, s0l, wh + OFF_W2, wl + OFF_W2, b2, part, nullptr, nullptr,
        512, 512, 0, 1, 0, ZC, ZW, ZB, PSTR);

    // obj -> fp16 (hi)
    obj_split_kernel<<<512, 256>>>(part, s1h);

    // relation tensor: (8, 128, 128, 128), single-term fp16, fused Wv
    final_tc_kernel<<<dim3(SS, LL), 256, REL_SMEM>>>(
        part, s1h, part + (size_t)2 * PSTR, part + (size_t)3 * PSTR, out);
}